// round 3
// baseline (speedup 1.0000x reference)
#include <cuda_runtime.h>
#include <cuda_bf16.h>
#include <cstdint>

#define NMAX 100000
#define NEG_SLOPE 0.2f

// ---------------- scratch (device globals; no allocation allowed) ----------------
__device__ float g_h[(size_t)NMAX * 256];          // [N, 256]: cols 0-127 layer1 (h0|h1), 128-255 layer2
__device__ float g_a[(size_t)NMAX * 8];            // per node: [as1h0,as1h1,ad1h0,ad1h1, as2h0,as2h1,ad2h0,ad2h1]
__device__ float g_den[(size_t)2 * NMAX * 2];      // [layer][node][head] softmax denominators
__device__ float g_out[(size_t)2 * NMAX * 128];    // [layer][node][128] aggregated messages

// ---------------- zero-init ----------------
__global__ void zero_kernel() {
    size_t i = (size_t)blockIdx.x * blockDim.x + threadIdx.x;
    size_t stride = (size_t)gridDim.x * blockDim.x;
    const float4 z = {0.f, 0.f, 0.f, 0.f};
    size_t n_out = (size_t)2 * NMAX * 128 / 4;
    float4* po = (float4*)g_out;
    for (size_t j = i; j < n_out; j += stride) po[j] = z;
    size_t n_den = (size_t)2 * NMAX * 2 / 4;
    float4* pd = (float4*)g_den;
    for (size_t j = i; j < n_den; j += stride) pd[j] = z;
}

// ---------------- GEMM: h = x @ [W1 | W2]  ([N,256] @ [256,256]) ----------------
// grid: (ceil(N/64), 4). Col-tile by: 0,1 -> W1 cols 0..127 ; 2,3 -> W2 cols 0..127.
__global__ __launch_bounds__(256) void gemm_h(const float* __restrict__ x,
                                              const float* __restrict__ W1,
                                              const float* __restrict__ W2,
                                              int N) {
    __shared__ float As[64][17];
    __shared__ float Bs[16][64];
    const int by = blockIdx.y;
    const float* __restrict__ W = (by < 2) ? W1 : W2;
    const int c0w = (by & 1) * 64;       // col offset within the chosen W
    const int r0 = blockIdx.x * 64;
    const int tid = threadIdx.x;
    const int tx = tid & 15, ty = tid >> 4;

    float acc[4][4] = {};
    for (int k0 = 0; k0 < 256; k0 += 16) {
        #pragma unroll
        for (int i = 0; i < 4; i++) {
            int idx = tid + i * 256;
            int row = idx >> 4, kk = idx & 15;
            float v = 0.f;
            int n = r0 + row;
            if (n < N) v = x[(size_t)n * 256 + k0 + kk];
            As[row][kk] = v;
        }
        #pragma unroll
        for (int i = 0; i < 4; i++) {
            int idx = tid + i * 256;
            int kk = idx >> 6, cc = idx & 63;
            Bs[kk][cc] = W[(size_t)(k0 + kk) * 128 + c0w + cc];
        }
        __syncthreads();
        #pragma unroll
        for (int kk = 0; kk < 16; kk++) {
            float ra[4], rb[4];
            #pragma unroll
            for (int i = 0; i < 4; i++) ra[i] = As[ty * 4 + i][kk];
            #pragma unroll
            for (int j = 0; j < 4; j++) rb[j] = Bs[kk][tx * 4 + j];
            #pragma unroll
            for (int i = 0; i < 4; i++)
                #pragma unroll
                for (int j = 0; j < 4; j++) acc[i][j] += ra[i] * rb[j];
        }
        __syncthreads();
    }
    const int cbase = by * 64;   // destination column base in g_h [0..255]
    #pragma unroll
    for (int i = 0; i < 4; i++) {
        int n = r0 + ty * 4 + i;
        if (n < N) {
            float4 v = make_float4(acc[i][0], acc[i][1], acc[i][2], acc[i][3]);
            *(float4*)&g_h[(size_t)n * 256 + cbase + tx * 4] = v;
        }
    }
}

// ---------------- per-node attention logits (warp per node) ----------------
__global__ __launch_bounds__(256) void att_kernel(const float* __restrict__ as1,
                                                  const float* __restrict__ ad1,
                                                  const float* __restrict__ as2,
                                                  const float* __restrict__ ad2,
                                                  int N) {
    int w = (int)(((size_t)blockIdx.x * blockDim.x + threadIdx.x) >> 5);
    int lane = threadIdx.x & 31;
    if (w >= N) return;
    const float* hr = g_h + (size_t)w * 256;
    float ss[4] = {0.f, 0.f, 0.f, 0.f};
    float sd[4] = {0.f, 0.f, 0.f, 0.f};
    #pragma unroll
    for (int k = 0; k < 8; k++) {
        int c = k >> 1;                       // chunk 0..3: L1H0,L1H1,L2H0,L2H1
        int pos = ((k & 1) << 5) + lane;      // position within 64-wide head chunk
        float v = hr[(k << 5) + lane];
        const float* pa = (c < 2 ? as1 : as2) + ((c & 1) << 6);
        const float* pd = (c < 2 ? ad1 : ad2) + ((c & 1) << 6);
        ss[c] += v * pa[pos];
        sd[c] += v * pd[pos];
    }
    #pragma unroll
    for (int c = 0; c < 4; c++) {
        #pragma unroll
        for (int off = 16; off; off >>= 1) {
            ss[c] += __shfl_down_sync(0xffffffffu, ss[c], off);
            sd[c] += __shfl_down_sync(0xffffffffu, sd[c], off);
        }
    }
    if (lane == 0) {
        float* o = g_a + (size_t)w * 8;
        o[0] = ss[0]; o[1] = ss[1]; o[2] = sd[0]; o[3] = sd[1];
        o[4] = ss[2]; o[5] = ss[3]; o[6] = sd[2]; o[7] = sd[3];
    }
}

// ---------------- edge pass 1: softmax denominators ----------------
__global__ __launch_bounds__(256) void edge_sum(const int* __restrict__ ei, int E, int N, int layer) {
    int i = blockIdx.x * blockDim.x + threadIdx.x;
    int T = E + N;
    if (i >= T) return;
    int s, d;
    if (i < E) { s = __ldg(&ei[i]); d = __ldg(&ei[E + i]); }
    else       { s = d = i - E; }
    const float* as = g_a + (size_t)s * 8 + layer * 4;
    const float* ad = g_a + (size_t)d * 8 + layer * 4 + 2;
    float e0 = as[0] + ad[0]; e0 = e0 > 0.f ? e0 : NEG_SLOPE * e0;
    float e1 = as[1] + ad[1]; e1 = e1 > 0.f ? e1 : NEG_SLOPE * e1;
    float* den = g_den + (size_t)layer * NMAX * 2;
    atomicAdd(&den[(size_t)d * 2 + 0], __expf(e0));
    atomicAdd(&den[(size_t)d * 2 + 1], __expf(e1));
}

// ---------------- edge pass 2: weighted message accumulation (warp per edge) ----------------
__global__ __launch_bounds__(256) void edge_accum(const int* __restrict__ ei, int E, int N, int layer) {
    size_t gt = (size_t)blockIdx.x * blockDim.x + threadIdx.x;
    int w = (int)(gt >> 5);
    int lane = threadIdx.x & 31;
    int T = E + N;
    if (w >= T) return;
    int s, d;
    if (w < E) { s = __ldg(&ei[w]); d = __ldg(&ei[E + w]); }
    else       { s = d = w - E; }
    float alpha = 0.f;
    if (lane < 2) {
        float av = g_a[(size_t)s * 8 + layer * 4 + lane];
        float dv = g_a[(size_t)d * 8 + layer * 4 + 2 + lane];
        float e = av + dv; e = e > 0.f ? e : NEG_SLOPE * e;
        alpha = __expf(e) / g_den[(size_t)layer * NMAX * 2 + (size_t)d * 2 + lane];
    }
    float a0 = __shfl_sync(0xffffffffu, alpha, 0);
    float a1 = __shfl_sync(0xffffffffu, alpha, 1);
    float al = (lane < 16) ? a0 : a1;   // lanes 0-15 -> head0 chunk, 16-31 -> head1 chunk
    const float4 hv = *(const float4*)(g_h + (size_t)s * 256 + layer * 128 + lane * 4);
    float4 v = make_float4(hv.x * al, hv.y * al, hv.z * al, hv.w * al);
    float4* dst = (float4*)(g_out + ((size_t)layer * NMAX + d) * 128 + lane * 4);
    atomicAdd(dst, v);   // sm_90+ vector atomic -> RED.128
}

// ---------------- final: y = relu(concat(outc+b1, outl+b2)) @ fcW + fcb ----------------
__global__ __launch_bounds__(256) void final_gemm(const float* __restrict__ b1,
                                                  const float* __restrict__ b2,
                                                  const float* __restrict__ fcW,
                                                  const float* __restrict__ fcb,
                                                  float* __restrict__ y,
                                                  int N) {
    __shared__ float As[64][17];
    __shared__ float Bs[16][64];
    const int r0 = blockIdx.x * 64;
    const int tid = threadIdx.x;
    const int tx = tid & 15, ty = tid >> 4;

    float acc[4][4] = {};
    for (int k0 = 0; k0 < 256; k0 += 16) {
        #pragma unroll
        for (int i = 0; i < 4; i++) {
            int idx = tid + i * 256;
            int row = idx >> 4, kk = idx & 15;
            int k = k0 + kk;
            int n = r0 + row;
            float v = 0.f;
            if (n < N) {
                if (k < 128) v = g_out[(size_t)n * 128 + k] + b1[k];
                else         v = g_out[((size_t)NMAX + n) * 128 + (k - 128)] + b2[k - 128];
                v = fmaxf(v, 0.f);
            }
            As[row][kk] = v;
        }
        #pragma unroll
        for (int i = 0; i < 4; i++) {
            int idx = tid + i * 256;
            int kk = idx >> 6, cc = idx & 63;
            Bs[kk][cc] = fcW[(size_t)(k0 + kk) * 64 + cc];
        }
        __syncthreads();
        #pragma unroll
        for (int kk = 0; kk < 16; kk++) {
            float ra[4], rb[4];
            #pragma unroll
            for (int i = 0; i < 4; i++) ra[i] = As[ty * 4 + i][kk];
            #pragma unroll
            for (int j = 0; j < 4; j++) rb[j] = Bs[kk][tx * 4 + j];
            #pragma unroll
            for (int i = 0; i < 4; i++)
                #pragma unroll
                for (int j = 0; j < 4; j++) acc[i][j] += ra[i] * rb[j];
        }
        __syncthreads();
    }
    #pragma unroll
    for (int i = 0; i < 4; i++) {
        int n = r0 + ty * 4 + i;
        if (n < N) {
            float4 v = make_float4(acc[i][0] + fcb[tx * 4 + 0],
                                   acc[i][1] + fcb[tx * 4 + 1],
                                   acc[i][2] + fcb[tx * 4 + 2],
                                   acc[i][3] + fcb[tx * 4 + 3]);
            *(float4*)&y[(size_t)n * 64 + tx * 4] = v;
        }
    }
}

// ---------------- launcher ----------------
extern "C" void kernel_launch(void* const* d_in, const int* in_sizes, int n_in,
                              void* d_out, int out_size) {
    const float* x    = (const float*)d_in[0];
    const int*   eic  = (const int*)  d_in[1];
    const int*   eil  = (const int*)  d_in[2];
    const float* W1   = (const float*)d_in[3];
    const float* as1  = (const float*)d_in[4];
    const float* ad1  = (const float*)d_in[5];
    const float* b1   = (const float*)d_in[6];
    const float* W2   = (const float*)d_in[7];
    const float* as2  = (const float*)d_in[8];
    const float* ad2  = (const float*)d_in[9];
    const float* b2   = (const float*)d_in[10];
    const float* fcW  = (const float*)d_in[11];
    const float* fcb  = (const float*)d_in[12];
    float* y = (float*)d_out;

    const int N  = in_sizes[0] / 256;
    const int E1 = in_sizes[1] / 2;
    const int E2 = in_sizes[2] / 2;

    // 1. zero accumulators + denominators
    zero_kernel<<<2048, 256>>>();

    // 2. h = x @ [W1|W2]
    gemm_h<<<dim3((N + 63) / 64, 4), 256>>>(x, W1, W2, N);

    // 3. per-node attention logits
    att_kernel<<<(N + 7) / 8, 256>>>(as1, ad1, as2, ad2, N);

    // 4. softmax denominators (per layer, self-loops appended)
    {
        int T1 = E1 + N, T2 = E2 + N;
        edge_sum<<<(T1 + 255) / 256, 256>>>(eic, E1, N, 0);
        edge_sum<<<(T2 + 255) / 256, 256>>>(eil, E2, N, 1);
    }

    // 5. message aggregation (warp per edge)
    {
        long long T1 = (long long)(E1 + N) * 32, T2 = (long long)(E2 + N) * 32;
        edge_accum<<<(unsigned)((T1 + 255) / 256), 256>>>(eic, E1, N, 0);
        edge_accum<<<(unsigned)((T2 + 255) / 256), 256>>>(eil, E2, N, 1);
    }

    // 6. bias + relu + concat + FC
    final_gemm<<<(N + 63) / 64, 256>>>(b1, b2, fcW, fcb, y, N);
}

// round 7
// speedup vs baseline: 1.2313x; 1.2313x over previous
#include <cuda_runtime.h>
#include <cuda_bf16.h>
#include <cstdint>

#define NMAX 100000
#define ECAP 1700000
#define NEG_SLOPE 0.2f

// ---------------- scratch (device globals; no allocation allowed) ----------------
__device__ float g_h[(size_t)NMAX * 256];            // [N,256]: cols 0-127 layer0 (h0|h1), 128-255 layer1
__device__ float g_a[(size_t)NMAX * 8];              // [as1h0,as1h1,ad1h0,ad1h1, as2h0,as2h1,ad2h0,ad2h1]
__device__ float g_out[(size_t)2 * NMAX * 128];      // [layer][node][128] normalized aggregates
__device__ int   g_deg[2 * NMAX];                    // per-layer in-degree
__device__ int   g_off[2 * (NMAX + 1)];              // per-layer CSR offsets
__device__ int   g_cur[2 * NMAX];                    // scatter cursors
__device__ int   g_srclist[(size_t)2 * ECAP];        // per-layer src ids grouped by dst

// ---------------- zero degree counters (only small state needs zeroing now) ------
__global__ void zero_deg() {
    int i = blockIdx.x * blockDim.x + threadIdx.x;
    if (i < 2 * NMAX) g_deg[i] = 0;
}

// ---------------- GEMM: h = x @ [W1 | W2]  ([N,256] @ [256,256]) ----------------
__global__ __launch_bounds__(256) void gemm_h(const float* __restrict__ x,
                                              const float* __restrict__ W1,
                                              const float* __restrict__ W2,
                                              int N) {
    __shared__ float As[64][17];
    __shared__ float Bs[16][64];
    const int by = blockIdx.y;
    const float* __restrict__ W = (by < 2) ? W1 : W2;
    const int c0w = (by & 1) * 64;
    const int r0 = blockIdx.x * 64;
    const int tid = threadIdx.x;
    const int tx = tid & 15, ty = tid >> 4;

    float acc[4][4] = {};
    for (int k0 = 0; k0 < 256; k0 += 16) {
        #pragma unroll
        for (int i = 0; i < 4; i++) {
            int idx = tid + i * 256;
            int row = idx >> 4, kk = idx & 15;
            float v = 0.f;
            int n = r0 + row;
            if (n < N) v = x[(size_t)n * 256 + k0 + kk];
            As[row][kk] = v;
        }
        #pragma unroll
        for (int i = 0; i < 4; i++) {
            int idx = tid + i * 256;
            int kk = idx >> 6, cc = idx & 63;
            Bs[kk][cc] = W[(size_t)(k0 + kk) * 128 + c0w + cc];
        }
        __syncthreads();
        #pragma unroll
        for (int kk = 0; kk < 16; kk++) {
            float ra[4], rb[4];
            #pragma unroll
            for (int i = 0; i < 4; i++) ra[i] = As[ty * 4 + i][kk];
            #pragma unroll
            for (int j = 0; j < 4; j++) rb[j] = Bs[kk][tx * 4 + j];
            #pragma unroll
            for (int i = 0; i < 4; i++)
                #pragma unroll
                for (int j = 0; j < 4; j++) acc[i][j] += ra[i] * rb[j];
        }
        __syncthreads();
    }
    const int cbase = by * 64;
    #pragma unroll
    for (int i = 0; i < 4; i++) {
        int n = r0 + ty * 4 + i;
        if (n < N) {
            float4 v = make_float4(acc[i][0], acc[i][1], acc[i][2], acc[i][3]);
            *(float4*)&g_h[(size_t)n * 256 + cbase + tx * 4] = v;
        }
    }
}

// ---------------- per-node attention logits (warp per node) ----------------
__global__ __launch_bounds__(256) void att_kernel(const float* __restrict__ as1,
                                                  const float* __restrict__ ad1,
                                                  const float* __restrict__ as2,
                                                  const float* __restrict__ ad2,
                                                  int N) {
    int w = (int)(((size_t)blockIdx.x * blockDim.x + threadIdx.x) >> 5);
    int lane = threadIdx.x & 31;
    if (w >= N) return;
    const float* hr = g_h + (size_t)w * 256;
    float ss[4] = {0.f, 0.f, 0.f, 0.f};
    float sd[4] = {0.f, 0.f, 0.f, 0.f};
    #pragma unroll
    for (int k = 0; k < 8; k++) {
        int c = k >> 1;
        int pos = ((k & 1) << 5) + lane;
        float v = hr[(k << 5) + lane];
        const float* pa = (c < 2 ? as1 : as2) + ((c & 1) << 6);
        const float* pd = (c < 2 ? ad1 : ad2) + ((c & 1) << 6);
        ss[c] += v * pa[pos];
        sd[c] += v * pd[pos];
    }
    #pragma unroll
    for (int c = 0; c < 4; c++) {
        #pragma unroll
        for (int off = 16; off; off >>= 1) {
            ss[c] += __shfl_down_sync(0xffffffffu, ss[c], off);
            sd[c] += __shfl_down_sync(0xffffffffu, sd[c], off);
        }
    }
    if (lane == 0) {
        float* o = g_a + (size_t)w * 8;
        o[0] = ss[0]; o[1] = ss[1]; o[2] = sd[0]; o[3] = sd[1];
        o[4] = ss[2]; o[5] = ss[3]; o[6] = sd[2]; o[7] = sd[3];
    }
}

// ---------------- CSR build: count, scan, scatter ----------------
__global__ __launch_bounds__(256) void count_kernel(const int* __restrict__ ei, int E, int layer) {
    int i = blockIdx.x * blockDim.x + threadIdx.x;
    if (i < E) {
        int d = __ldg(&ei[E + i]);
        atomicAdd(&g_deg[layer * NMAX + d], 1);
    }
}

__global__ __launch_bounds__(1024) void scan_kernel(int N) {
    const int layer = blockIdx.x;
    const int* deg = g_deg + layer * NMAX;
    int* off = g_off + layer * (NMAX + 1);
    int* cur = g_cur + layer * NMAX;
    __shared__ int sh[1024];
    const int tid = threadIdx.x;
    const int chunk = (N + 1023) >> 10;
    const int lo = tid * chunk;
    const int hi = min(lo + chunk, N);
    int s = 0;
    for (int i = lo; i < hi; i++) s += deg[i];
    sh[tid] = s;
    __syncthreads();
    // Hillis-Steele inclusive scan over 1024 partials
    for (int o = 1; o < 1024; o <<= 1) {
        int v = sh[tid];
        int add = (tid >= o) ? sh[tid - o] : 0;
        __syncthreads();
        sh[tid] = v + add;
        __syncthreads();
    }
    int run = (tid == 0) ? 0 : sh[tid - 1];
    for (int i = lo; i < hi; i++) {
        off[i] = run;
        cur[i] = run;
        run += deg[i];
    }
    if (tid == 1023) off[N] = sh[1023];
}

__global__ __launch_bounds__(256) void scatter_kernel(const int* __restrict__ ei, int E, int layer) {
    int i = blockIdx.x * blockDim.x + threadIdx.x;
    if (i < E) {
        int s = __ldg(&ei[i]);
        int d = __ldg(&ei[E + i]);
        int p = atomicAdd(&g_cur[layer * NMAX + d], 1);
        g_srclist[(size_t)layer * ECAP + p] = s;
    }
}

// ---------------- aggregation: warp per (node, layer), no atomics ----------------
__global__ __launch_bounds__(256) void aggregate(int N) {
    const int layer = blockIdx.y;
    const int d = blockIdx.x * 8 + (threadIdx.x >> 5);
    const int lane = threadIdx.x & 31;
    if (d >= N) return;

    const float* arow = g_a + (size_t)d * 8 + layer * 4;
    const float ad0 = arow[2], ad1 = arow[3];

    // self loop
    float e0 = arow[0] + ad0; e0 = e0 > 0.f ? e0 : NEG_SLOPE * e0;
    float e1 = arow[1] + ad1; e1 = e1 > 0.f ? e1 : NEG_SLOPE * e1;
    float w0 = __expf(e0), w1 = __expf(e1);
    float den0 = w0, den1 = w1;
    const float4 hself = *(const float4*)(g_h + (size_t)d * 256 + layer * 128 + lane * 4);
    float ws = (lane < 16) ? w0 : w1;
    float4 acc = make_float4(ws * hself.x, ws * hself.y, ws * hself.z, ws * hself.w);

    const int beg = g_off[layer * (NMAX + 1) + d];
    const int end = g_off[layer * (NMAX + 1) + d + 1];
    const int* __restrict__ sl = g_srclist + (size_t)layer * ECAP;

    for (int e = beg; e < end; e++) {
        int s = __ldg(&sl[e]);
        const float2 av = __ldg((const float2*)(g_a + (size_t)s * 8 + layer * 4));
        float f0 = av.x + ad0; f0 = f0 > 0.f ? f0 : NEG_SLOPE * f0;
        float f1 = av.y + ad1; f1 = f1 > 0.f ? f1 : NEG_SLOPE * f1;
        float u0 = __expf(f0), u1 = __expf(f1);
        den0 += u0; den1 += u1;
        float uu = (lane < 16) ? u0 : u1;
        const float4 hv = __ldg((const float4*)(g_h + (size_t)s * 256 + layer * 128 + lane * 4));
        acc.x += uu * hv.x;
        acc.y += uu * hv.y;
        acc.z += uu * hv.z;
        acc.w += uu * hv.w;
    }

    const float inv = 1.f / ((lane < 16) ? den0 : den1);
    acc.x *= inv; acc.y *= inv; acc.z *= inv; acc.w *= inv;
    *(float4*)(g_out + ((size_t)layer * NMAX + d) * 128 + lane * 4) = acc;
}

// ---------------- final: y = relu(concat(outc+b1, outl+b2)) @ fcW + fcb ----------------
__global__ __launch_bounds__(256) void final_gemm(const float* __restrict__ b1,
                                                  const float* __restrict__ b2,
                                                  const float* __restrict__ fcW,
                                                  const float* __restrict__ fcb,
                                                  float* __restrict__ y,
                                                  int N) {
    __shared__ float As[64][17];
    __shared__ float Bs[16][64];
    const int r0 = blockIdx.x * 64;
    const int tid = threadIdx.x;
    const int tx = tid & 15, ty = tid >> 4;

    float acc[4][4] = {};
    for (int k0 = 0; k0 < 256; k0 += 16) {
        #pragma unroll
        for (int i = 0; i < 4; i++) {
            int idx = tid + i * 256;
            int row = idx >> 4, kk = idx & 15;
            int k = k0 + kk;
            int n = r0 + row;
            float v = 0.f;
            if (n < N) {
                if (k < 128) v = g_out[(size_t)n * 128 + k] + b1[k];
                else         v = g_out[((size_t)NMAX + n) * 128 + (k - 128)] + b2[k - 128];
                v = fmaxf(v, 0.f);
            }
            As[row][kk] = v;
        }
        #pragma unroll
        for (int i = 0; i < 4; i++) {
            int idx = tid + i * 256;
            int kk = idx >> 6, cc = idx & 63;
            Bs[kk][cc] = fcW[(size_t)(k0 + kk) * 64 + cc];
        }
        __syncthreads();
        #pragma unroll
        for (int kk = 0; kk < 16; kk++) {
            float ra[4], rb[4];
            #pragma unroll
            for (int i = 0; i < 4; i++) ra[i] = As[ty * 4 + i][kk];
            #pragma unroll
            for (int j = 0; j < 4; j++) rb[j] = Bs[kk][tx * 4 + j];
            #pragma unroll
            for (int i = 0; i < 4; i++)
                #pragma unroll
                for (int j = 0; j < 4; j++) acc[i][j] += ra[i] * rb[j];
        }
        __syncthreads();
    }
    #pragma unroll
    for (int i = 0; i < 4; i++) {
        int n = r0 + ty * 4 + i;
        if (n < N) {
            float4 v = make_float4(acc[i][0] + fcb[tx * 4 + 0],
                                   acc[i][1] + fcb[tx * 4 + 1],
                                   acc[i][2] + fcb[tx * 4 + 2],
                                   acc[i][3] + fcb[tx * 4 + 3]);
            *(float4*)&y[(size_t)n * 64 + tx * 4] = v;
        }
    }
}

// ---------------- launcher ----------------
extern "C" void kernel_launch(void* const* d_in, const int* in_sizes, int n_in,
                              void* d_out, int out_size) {
    const float* x    = (const float*)d_in[0];
    const int*   eic  = (const int*)  d_in[1];
    const int*   eil  = (const int*)  d_in[2];
    const float* W1   = (const float*)d_in[3];
    const float* as1  = (const float*)d_in[4];
    const float* ad1  = (const float*)d_in[5];
    const float* b1   = (const float*)d_in[6];
    const float* W2   = (const float*)d_in[7];
    const float* as2  = (const float*)d_in[8];
    const float* ad2  = (const float*)d_in[9];
    const float* b2   = (const float*)d_in[10];
    const float* fcW  = (const float*)d_in[11];
    const float* fcb  = (const float*)d_in[12];
    float* y = (float*)d_out;

    const int N  = in_sizes[0] / 256;
    const int E1 = in_sizes[1] / 2;
    const int E2 = in_sizes[2] / 2;

    // 1. zero degree counters (tiny)
    zero_deg<<<(2 * NMAX + 255) / 256, 256>>>();

    // 2. h = x @ [W1|W2]
    gemm_h<<<dim3((N + 63) / 64, 4), 256>>>(x, W1, W2, N);

    // 3. per-node attention logits
    att_kernel<<<(N + 7) / 8, 256>>>(as1, ad1, as2, ad2, N);

    // 4. CSR build (by destination) for both layers
    count_kernel<<<(E1 + 255) / 256, 256>>>(eic, E1, 0);
    count_kernel<<<(E2 + 255) / 256, 256>>>(eil, E2, 1);
    scan_kernel<<<2, 1024>>>(N);
    scatter_kernel<<<(E1 + 255) / 256, 256>>>(eic, E1, 0);
    scatter_kernel<<<(E2 + 255) / 256, 256>>>(eil, E2, 1);

    // 5. gather-based softmax aggregation (no atomics, single pass, in-register normalize)
    aggregate<<<dim3((N + 7) / 8, 2), 256>>>(N);

    // 6. bias + relu + concat + FC
    final_gemm<<<(N + 63) / 64, 256>>>(b1, b2, fcW, fcb, y, N);
}

// round 10
// speedup vs baseline: 1.2385x; 1.0058x over previous
#include <cuda_runtime.h>
#include <cuda_fp16.h>
#include <cuda_bf16.h>
#include <cstdint>

#define NMAX 100000
#define ECAP 1700000
#define NEG_SLOPE 0.2f

// ---------------- scratch (device globals; no allocation allowed) ----------------
__device__ __half g_hh[(size_t)2 * NMAX * 128];      // [layer][node][128] fp16 features (gather path)
__device__ float  g_as[(size_t)2 * NMAX * 2];        // [layer][node][head] a_src logits
__device__ float  g_ad[(size_t)2 * NMAX * 2];        // [layer][node][head] a_dst logits
__device__ float  g_out[(size_t)2 * NMAX * 128];     // [layer][node][128] normalized aggregates
__device__ int    g_deg[2 * NMAX];                   // per-layer in-degree
__device__ int    g_off[2 * (NMAX + 1)];             // per-layer CSR offsets
__device__ int    g_cur[2 * NMAX];                   // scatter cursors
__device__ int    g_srclist[(size_t)2 * ECAP];       // per-layer src ids grouped by dst

__device__ __forceinline__ float4 h4_to_f4(uint2 u) {
    __half2 a = *(__half2*)&u.x;
    __half2 b = *(__half2*)&u.y;
    float2 fa = __half22float2(a), fb = __half22float2(b);
    return make_float4(fa.x, fa.y, fb.x, fb.y);
}
__device__ __forceinline__ float lrelu(float v) { return v > 0.f ? v : NEG_SLOPE * v; }

// ---------------- zero degree counters ----------------
__global__ void zero_deg() {
    int i = blockIdx.x * blockDim.x + threadIdx.x;
    if (i < 2 * NMAX) g_deg[i] = 0;
}

// ---------------- GEMM: h = x @ [W1 | W2] -> fp16, layer-major layout ----------------
// grid: (ceil(N/64), 4). by: 0,1 -> layer0 (W1) col 0/64 ; 2,3 -> layer1 (W2) col 0/64.
__global__ __launch_bounds__(256) void gemm_h(const float* __restrict__ x,
                                              const float* __restrict__ W1,
                                              const float* __restrict__ W2,
                                              int N) {
    __shared__ float As[64][17];
    __shared__ float Bs[16][64];
    const int by = blockIdx.y;
    const int layer = by >> 1;
    const float* __restrict__ W = layer ? W2 : W1;
    const int c0w = (by & 1) * 64;
    const int r0 = blockIdx.x * 64;
    const int tid = threadIdx.x;
    const int tx = tid & 15, ty = tid >> 4;

    float acc[4][4] = {};
    for (int k0 = 0; k0 < 256; k0 += 16) {
        #pragma unroll
        for (int i = 0; i < 4; i++) {
            int idx = tid + i * 256;
            int row = idx >> 4, kk = idx & 15;
            float v = 0.f;
            int n = r0 + row;
            if (n < N) v = x[(size_t)n * 256 + k0 + kk];
            As[row][kk] = v;
        }
        #pragma unroll
        for (int i = 0; i < 4; i++) {
            int idx = tid + i * 256;
            int kk = idx >> 6, cc = idx & 63;
            Bs[kk][cc] = W[(size_t)(k0 + kk) * 128 + c0w + cc];
        }
        __syncthreads();
        #pragma unroll
        for (int kk = 0; kk < 16; kk++) {
            float ra[4], rb[4];
            #pragma unroll
            for (int i = 0; i < 4; i++) ra[i] = As[ty * 4 + i][kk];
            #pragma unroll
            for (int j = 0; j < 4; j++) rb[j] = Bs[kk][tx * 4 + j];
            #pragma unroll
            for (int i = 0; i < 4; i++)
                #pragma unroll
                for (int j = 0; j < 4; j++) acc[i][j] += ra[i] * rb[j];
        }
        __syncthreads();
    }
    #pragma unroll
    for (int i = 0; i < 4; i++) {
        int n = r0 + ty * 4 + i;
        if (n < N) {
            __half2 p0 = __floats2half2_rn(acc[i][0], acc[i][1]);
            __half2 p1 = __floats2half2_rn(acc[i][2], acc[i][3]);
            uint2 u;
            u.x = *(unsigned*)&p0;
            u.y = *(unsigned*)&p1;
            *(uint2*)(g_hh + ((size_t)layer * NMAX + n) * 128 + c0w + tx * 4) = u;
        }
    }
}

// ---------------- per-node attention logits (warp per node, fp16 h) ----------------
__global__ __launch_bounds__(256) void att_kernel(const float* __restrict__ as1,
                                                  const float* __restrict__ ad1,
                                                  const float* __restrict__ as2,
                                                  const float* __restrict__ ad2,
                                                  int N) {
    int w = (int)(((size_t)blockIdx.x * blockDim.x + threadIdx.x) >> 5);
    int lane = threadIdx.x & 31;
    if (w >= N) return;
    const int p0 = lane * 4;   // att arrays are [2][64] contiguous = 128 floats; h pos == att pos
    #pragma unroll
    for (int l = 0; l < 2; l++) {
        const float* __restrict__ pa = l ? as2 : as1;
        const float* __restrict__ pd = l ? ad2 : ad1;
        uint2 q = __ldg((const uint2*)(g_hh + ((size_t)l * NMAX + w) * 128) + lane);
        float4 f = h4_to_f4(q);
        float ss = f.x * pa[p0] + f.y * pa[p0 + 1] + f.z * pa[p0 + 2] + f.w * pa[p0 + 3];
        float sd = f.x * pd[p0] + f.y * pd[p0 + 1] + f.z * pd[p0 + 2] + f.w * pd[p0 + 3];
        #pragma unroll
        for (int off = 8; off; off >>= 1) {   // reduce within each half-warp (one head each)
            ss += __shfl_down_sync(0xffffffffu, ss, off, 16);
            sd += __shfl_down_sync(0xffffffffu, sd, off, 16);
        }
        if ((lane & 15) == 0) {
            int head = lane >> 4;
            g_as[((size_t)l * NMAX + w) * 2 + head] = ss;
            g_ad[((size_t)l * NMAX + w) * 2 + head] = sd;
        }
    }
}

// ---------------- CSR build: count, scan, scatter ----------------
__global__ __launch_bounds__(256) void count_kernel(const int* __restrict__ ei, int E, int layer) {
    int i = blockIdx.x * blockDim.x + threadIdx.x;
    if (i < E) {
        int d = __ldg(&ei[E + i]);
        atomicAdd(&g_deg[layer * NMAX + d], 1);
    }
}

__global__ __launch_bounds__(1024) void scan_kernel(int N) {
    const int layer = blockIdx.x;
    const int* deg = g_deg + layer * NMAX;
    int* off = g_off + layer * (NMAX + 1);
    int* cur = g_cur + layer * NMAX;
    __shared__ int sh[1024];
    const int tid = threadIdx.x;
    const int chunk = (N + 1023) >> 10;
    const int lo = tid * chunk;
    const int hi = min(lo + chunk, N);
    int s = 0;
    for (int i = lo; i < hi; i++) s += deg[i];
    sh[tid] = s;
    __syncthreads();
    for (int o = 1; o < 1024; o <<= 1) {
        int v = sh[tid];
        int add = (tid >= o) ? sh[tid - o] : 0;
        __syncthreads();
        sh[tid] = v + add;
        __syncthreads();
    }
    int run = (tid == 0) ? 0 : sh[tid - 1];
    for (int i = lo; i < hi; i++) {
        off[i] = run;
        cur[i] = run;
        run += deg[i];
    }
    if (tid == 1023) off[N] = sh[1023];
}

__global__ __launch_bounds__(256) void scatter_kernel(const int* __restrict__ ei, int E, int layer) {
    int i = blockIdx.x * blockDim.x + threadIdx.x;
    if (i < E) {
        int s = __ldg(&ei[i]);
        int d = __ldg(&ei[E + i]);
        int p = atomicAdd(&g_cur[layer * NMAX + d], 1);
        g_srclist[(size_t)layer * ECAP + p] = s;
    }
}

// ---------------- aggregation: warp per (node, layer), fp16 gathers, unroll-2 ----------------
__global__ __launch_bounds__(256) void aggregate(int N) {
    const int layer = blockIdx.y;
    const int d = blockIdx.x * 8 + (threadIdx.x >> 5);
    const int lane = threadIdx.x & 31;
    if (d >= N) return;

    const __half* __restrict__ hbase = g_hh + (size_t)layer * NMAX * 128;
    const float* __restrict__ asb = g_as + (size_t)layer * NMAX * 2;
    const float2 adv = __ldg((const float2*)(g_ad + ((size_t)layer * NMAX + d) * 2));
    const float ad0 = adv.x, ad1 = adv.y;

    // self loop
    const float2 asd = __ldg((const float2*)(asb + (size_t)d * 2));
    float w0 = __expf(lrelu(asd.x + ad0));
    float w1 = __expf(lrelu(asd.y + ad1));
    float den0 = w0, den1 = w1;
    float4 hs = h4_to_f4(__ldg((const uint2*)(hbase + (size_t)d * 128) + lane));
    float ws = (lane < 16) ? w0 : w1;
    float4 acc = make_float4(ws * hs.x, ws * hs.y, ws * hs.z, ws * hs.w);

    const int beg = g_off[layer * (NMAX + 1) + d];
    const int end = g_off[layer * (NMAX + 1) + d + 1];
    const int* __restrict__ sl = g_srclist + (size_t)layer * ECAP;

    int e = beg;
    for (; e + 2 <= end; e += 2) {
        // batch all independent loads first (MLP)
        const int s0 = __ldg(&sl[e]);
        const int s1 = __ldg(&sl[e + 1]);
        const float2 a0 = __ldg((const float2*)(asb + (size_t)s0 * 2));
        const float2 a1 = __ldg((const float2*)(asb + (size_t)s1 * 2));
        const uint2 q0 = __ldg((const uint2*)(hbase + (size_t)s0 * 128) + lane);
        const uint2 q1 = __ldg((const uint2*)(hbase + (size_t)s1 * 128) + lane);

        float u00 = __expf(lrelu(a0.x + ad0));
        float u01 = __expf(lrelu(a0.y + ad1));
        float u10 = __expf(lrelu(a1.x + ad0));
        float u11 = __expf(lrelu(a1.y + ad1));
        den0 += u00 + u10;
        den1 += u01 + u11;
        float uu0 = (lane < 16) ? u00 : u01;
        float uu1 = (lane < 16) ? u10 : u11;
        float4 f0 = h4_to_f4(q0);
        float4 f1 = h4_to_f4(q1);
        acc.x += uu0 * f0.x + uu1 * f1.x;
        acc.y += uu0 * f0.y + uu1 * f1.y;
        acc.z += uu0 * f0.z + uu1 * f1.z;
        acc.w += uu0 * f0.w + uu1 * f1.w;
    }
    if (e < end) {
        const int s0 = __ldg(&sl[e]);
        const float2 a0 = __ldg((const float2*)(asb + (size_t)s0 * 2));
        const uint2 q0 = __ldg((const uint2*)(hbase + (size_t)s0 * 128) + lane);
        float u00 = __expf(lrelu(a0.x + ad0));
        float u01 = __expf(lrelu(a0.y + ad1));
        den0 += u00;
        den1 += u01;
        float uu0 = (lane < 16) ? u00 : u01;
        float4 f0 = h4_to_f4(q0);
        acc.x += uu0 * f0.x;
        acc.y += uu0 * f0.y;
        acc.z += uu0 * f0.z;
        acc.w += uu0 * f0.w;
    }

    const float inv = 1.f / ((lane < 16) ? den0 : den1);
    acc.x *= inv; acc.y *= inv; acc.z *= inv; acc.w *= inv;
    *(float4*)(g_out + ((size_t)layer * NMAX + d) * 128 + lane * 4) = acc;
}

// ---------------- final: y = relu(concat(outc+b1, outl+b2)) @ fcW + fcb ----------------
__global__ __launch_bounds__(256) void final_gemm(const float* __restrict__ b1,
                                                  const float* __restrict__ b2,
                                                  const float* __restrict__ fcW,
                                                  const float* __restrict__ fcb,
                                                  float* __restrict__ y,
                                                  int N) {
    __shared__ float As[64][17];
    __shared__ float Bs[16][64];
    const int r0 = blockIdx.x * 64;
    const int tid = threadIdx.x;
    const int tx = tid & 15, ty = tid >> 4;

    float acc[4][4] = {};
    for (int k0 = 0; k0 < 256; k0 += 16) {
        #pragma unroll
        for (int i = 0; i < 4; i++) {
            int idx = tid + i * 256;
            int row = idx >> 4, kk = idx & 15;
            int k = k0 + kk;
            int n = r0 + row;
            float v = 0.f;
            if (n < N) {
                if (k < 128) v = g_out[(size_t)n * 128 + k] + b1[k];
                else         v = g_out[((size_t)NMAX + n) * 128 + (k - 128)] + b2[k - 128];
                v = fmaxf(v, 0.f);
            }
            As[row][kk] = v;
        }
        #pragma unroll
        for (int i = 0; i < 4; i++) {
            int idx = tid + i * 256;
            int kk = idx >> 6, cc = idx & 63;
            Bs[kk][cc] = fcW[(size_t)(k0 + kk) * 64 + cc];
        }
        __syncthreads();
        #pragma unroll
        for (int kk = 0; kk < 16; kk++) {
            float ra[4], rb[4];
            #pragma unroll
            for (int i = 0; i < 4; i++) ra[i] = As[ty * 4 + i][kk];
            #pragma unroll
            for (int j = 0; j < 4; j++) rb[j] = Bs[kk][tx * 4 + j];
            #pragma unroll
            for (int i = 0; i < 4; i++)
                #pragma unroll
                for (int j = 0; j < 4; j++) acc[i][j] += ra[i] * rb[j];
        }
        __syncthreads();
    }
    #pragma unroll
    for (int i = 0; i < 4; i++) {
        int n = r0 + ty * 4 + i;
        if (n < N) {
            float4 v = make_float4(acc[i][0] + fcb[tx * 4 + 0],
                                   acc[i][1] + fcb[tx * 4 + 1],
                                   acc[i][2] + fcb[tx * 4 + 2],
                                   acc[i][3] + fcb[tx * 4 + 3]);
            *(float4*)&y[(size_t)n * 64 + tx * 4] = v;
        }
    }
}

// ---------------- launcher ----------------
extern "C" void kernel_launch(void* const* d_in, const int* in_sizes, int n_in,
                              void* d_out, int out_size) {
    const float* x    = (const float*)d_in[0];
    const int*   eic  = (const int*)  d_in[1];
    const int*   eil  = (const int*)  d_in[2];
    const float* W1   = (const float*)d_in[3];
    const float* as1  = (const float*)d_in[4];
    const float* ad1  = (const float*)d_in[5];
    const float* b1   = (const float*)d_in[6];
    const float* W2   = (const float*)d_in[7];
    const float* as2  = (const float*)d_in[8];
    const float* ad2  = (const float*)d_in[9];
    const float* b2   = (const float*)d_in[10];
    const float* fcW  = (const float*)d_in[11];
    const float* fcb  = (const float*)d_in[12];
    float* y = (float*)d_out;

    const int N  = in_sizes[0] / 256;
    const int E1 = in_sizes[1] / 2;
    const int E2 = in_sizes[2] / 2;

    // 1. zero degree counters
    zero_deg<<<(2 * NMAX + 255) / 256, 256>>>();

    // 2. h = x @ [W1|W2] -> fp16 layer-major
    gemm_h<<<dim3((N + 63) / 64, 4), 256>>>(x, W1, W2, N);

    // 3. per-node attention logits
    att_kernel<<<(N + 7) / 8, 256>>>(as1, ad1, as2, ad2, N);

    // 4. CSR build (by destination) for both layers
    count_kernel<<<(E1 + 255) / 256, 256>>>(eic, E1, 0);
    count_kernel<<<(E2 + 255) / 256, 256>>>(eil, E2, 1);
    scan_kernel<<<2, 1024>>>(N);
    scatter_kernel<<<(E1 + 255) / 256, 256>>>(eic, E1, 0);
    scatter_kernel<<<(E2 + 255) / 256, 256>>>(eil, E2, 1);

    // 5. gather-based softmax aggregation (fp16 gathers, L2-resident, unroll-2)
    aggregate<<<dim3((N + 7) / 8, 2), 256>>>(N);

    // 6. bias + relu + concat + FC
    final_gemm<<<(N + 63) / 64, 256>>>(b1, b2, fcW, fcb, y, N);
}

// round 14
// speedup vs baseline: 1.9263x; 1.5554x over previous
#include <cuda_runtime.h>
#include <cuda_fp16.h>
#include <cuda_bf16.h>
#include <cstdint>

#define NMAX 100000
#define ECAP 1700000
#define NEG_SLOPE 0.2f

// ---------------- scratch (device globals; no allocation allowed) ----------------
__device__ __half g_hh[(size_t)2 * NMAX * 128];      // [layer][node][128] fp16 features (gather path)
__device__ float  g_as[(size_t)2 * NMAX * 2];        // [layer][node][head] a_src logits
__device__ float  g_ad[(size_t)2 * NMAX * 2];        // [layer][node][head] a_dst logits
__device__ float  g_out[(size_t)2 * NMAX * 128];     // [layer][node][128] normalized aggregates
__device__ int    g_deg[2 * NMAX];
__device__ int    g_off[2 * (NMAX + 1)];
__device__ int    g_cur[2 * NMAX];
__device__ int    g_srclist[(size_t)2 * ECAP];

__device__ __forceinline__ float4 h4_to_f4(uint2 u) {
    __half2 a = *(__half2*)&u.x;
    __half2 b = *(__half2*)&u.y;
    float2 fa = __half22float2(a), fb = __half22float2(b);
    return make_float4(fa.x, fa.y, fb.x, fb.y);
}
__device__ __forceinline__ float lrelu(float v) { return v > 0.f ? v : NEG_SLOPE * v; }
__device__ __forceinline__ unsigned f2tf32(float f) {
    unsigned r;
    asm("cvt.rna.tf32.f32 %0, %1;" : "=r"(r) : "f"(f));
    return r;
}
__device__ __forceinline__ void mma_tf32(float* c, const unsigned* a, const unsigned* b) {
    asm volatile(
        "mma.sync.aligned.m16n8k8.row.col.f32.tf32.tf32.f32 "
        "{%0,%1,%2,%3}, {%4,%5,%6,%7}, {%8,%9}, {%0,%1,%2,%3};"
        : "+f"(c[0]), "+f"(c[1]), "+f"(c[2]), "+f"(c[3])
        : "r"(a[0]), "r"(a[1]), "r"(a[2]), "r"(a[3]), "r"(b[0]), "r"(b[1]));
}

// ---------------- zero degree counters ----------------
__global__ void zero_deg() {
    int i = blockIdx.x * blockDim.x + threadIdx.x;
    if (i < 2 * NMAX) g_deg[i] = 0;
}

// ---------------- tensor-core GEMM: h = x @ W(layer) -> fp16 g_hh ----------------
// block = 256 thr (8 warps as 4m x 2n), tile 128 rows x 128 cols, K=256 panels of 16.
__global__ __launch_bounds__(256) void gemm_h_tc(const float* __restrict__ x,
                                                 const float* __restrict__ W1,
                                                 const float* __restrict__ W2,
                                                 int N) {
    __shared__ float As[128][20];     // [m][k] pad 20 (conflict-free frag reads)
    __shared__ float Bs[16][136];     // [k][n] pad 136
    const int layer = blockIdx.y;
    const float* __restrict__ W = layer ? W2 : W1;
    const int r0 = blockIdx.x * 128;
    const int tid = threadIdx.x;
    const int wid = tid >> 5, lane = tid & 31;
    const int gid = lane >> 2, q = lane & 3;
    const int m0w = (wid & 3) * 32;   // warp row offset
    const int n0w = (wid >> 2) * 64;  // warp col offset

    float c[2][8][4];
    #pragma unroll
    for (int i = 0; i < 2; i++)
        #pragma unroll
        for (int j = 0; j < 8; j++)
            #pragma unroll
            for (int k = 0; k < 4; k++) c[i][j][k] = 0.f;

    for (int k0 = 0; k0 < 256; k0 += 16) {
        // load A panel 128x16 (512 float4, 2/thread)
        #pragma unroll
        for (int i = 0; i < 2; i++) {
            int lin = tid + i * 256;
            int row = lin >> 2, c4 = (lin & 3) * 4;
            float4 v = make_float4(0.f, 0.f, 0.f, 0.f);
            int n = r0 + row;
            if (n < N) v = *(const float4*)&x[(size_t)n * 256 + k0 + c4];
            *(float4*)&As[row][c4] = v;
        }
        // load B panel 16x128 (512 float4, 2/thread)
        #pragma unroll
        for (int i = 0; i < 2; i++) {
            int lin = tid + i * 256;
            int kk = lin >> 5, n4 = (lin & 31) * 4;
            *(float4*)&Bs[kk][n4] = *(const float4*)&W[(size_t)(k0 + kk) * 128 + n4];
        }
        __syncthreads();

        #pragma unroll
        for (int sub = 0; sub < 2; sub++) {
            const int kk = sub * 8;
            unsigned a[2][4], b[8][2];
            #pragma unroll
            for (int mt = 0; mt < 2; mt++) {
                int m = m0w + mt * 16 + gid;
                a[mt][0] = f2tf32(As[m][kk + q]);
                a[mt][1] = f2tf32(As[m + 8][kk + q]);
                a[mt][2] = f2tf32(As[m][kk + q + 4]);
                a[mt][3] = f2tf32(As[m + 8][kk + q + 4]);
            }
            #pragma unroll
            for (int nt = 0; nt < 8; nt++) {
                int n = n0w + nt * 8 + gid;
                b[nt][0] = f2tf32(Bs[kk + q][n]);
                b[nt][1] = f2tf32(Bs[kk + q + 4][n]);
            }
            #pragma unroll
            for (int mt = 0; mt < 2; mt++)
                #pragma unroll
                for (int nt = 0; nt < 8; nt++) mma_tf32(c[mt][nt], a[mt], b[nt]);
        }
        __syncthreads();
    }

    // store fp16
    __half* __restrict__ hb = g_hh + (size_t)layer * NMAX * 128;
    #pragma unroll
    for (int mt = 0; mt < 2; mt++) {
        #pragma unroll
        for (int nt = 0; nt < 8; nt++) {
            int col = n0w + nt * 8 + 2 * q;
            int r = r0 + m0w + mt * 16 + gid;
            if (r < N) {
                __half2 p = __floats2half2_rn(c[mt][nt][0], c[mt][nt][1]);
                *(__half2*)(hb + (size_t)r * 128 + col) = p;
            }
            if (r + 8 < N) {
                __half2 p = __floats2half2_rn(c[mt][nt][2], c[mt][nt][3]);
                *(__half2*)(hb + (size_t)(r + 8) * 128 + col) = p;
            }
        }
    }
}

// ---------------- per-node attention logits (warp per node, fp16 h) ----------------
__global__ __launch_bounds__(256) void att_kernel(const float* __restrict__ as1,
                                                  const float* __restrict__ ad1,
                                                  const float* __restrict__ as2,
                                                  const float* __restrict__ ad2,
                                                  int N) {
    int w = (int)(((size_t)blockIdx.x * blockDim.x + threadIdx.x) >> 5);
    int lane = threadIdx.x & 31;
    if (w >= N) return;
    const int p0 = lane * 4;
    #pragma unroll
    for (int l = 0; l < 2; l++) {
        const float* __restrict__ pa = l ? as2 : as1;
        const float* __restrict__ pd = l ? ad2 : ad1;
        uint2 qv = __ldg((const uint2*)(g_hh + ((size_t)l * NMAX + w) * 128) + lane);
        float4 f = h4_to_f4(qv);
        float ss = f.x * pa[p0] + f.y * pa[p0 + 1] + f.z * pa[p0 + 2] + f.w * pa[p0 + 3];
        float sd = f.x * pd[p0] + f.y * pd[p0 + 1] + f.z * pd[p0 + 2] + f.w * pd[p0 + 3];
        #pragma unroll
        for (int off = 8; off; off >>= 1) {
            ss += __shfl_down_sync(0xffffffffu, ss, off, 16);
            sd += __shfl_down_sync(0xffffffffu, sd, off, 16);
        }
        if ((lane & 15) == 0) {
            int head = lane >> 4;
            g_as[((size_t)l * NMAX + w) * 2 + head] = ss;
            g_ad[((size_t)l * NMAX + w) * 2 + head] = sd;
        }
    }
}

// ---------------- CSR build ----------------
__global__ __launch_bounds__(256) void count_kernel(const int* __restrict__ ei, int E, int layer) {
    int i = blockIdx.x * blockDim.x + threadIdx.x;
    if (i < E) {
        int d = __ldg(&ei[E + i]);
        atomicAdd(&g_deg[layer * NMAX + d], 1);
    }
}

__global__ __launch_bounds__(1024) void scan_kernel(int N) {
    const int layer = blockIdx.x;
    const int* deg = g_deg + layer * NMAX;
    int* off = g_off + layer * (NMAX + 1);
    int* cur = g_cur + layer * NMAX;
    __shared__ int sh[1024];
    const int tid = threadIdx.x;
    const int chunk = (N + 1023) >> 10;
    const int lo = tid * chunk;
    const int hi = min(lo + chunk, N);
    int s = 0;
    for (int i = lo; i < hi; i++) s += deg[i];
    sh[tid] = s;
    __syncthreads();
    for (int o = 1; o < 1024; o <<= 1) {
        int v = sh[tid];
        int add = (tid >= o) ? sh[tid - o] : 0;
        __syncthreads();
        sh[tid] = v + add;
        __syncthreads();
    }
    int run = (tid == 0) ? 0 : sh[tid - 1];
    for (int i = lo; i < hi; i++) {
        off[i] = run;
        cur[i] = run;
        run += deg[i];
    }
    if (tid == 1023) off[N] = sh[1023];
}

__global__ __launch_bounds__(256) void scatter_kernel(const int* __restrict__ ei, int E, int layer) {
    int i = blockIdx.x * blockDim.x + threadIdx.x;
    if (i < E) {
        int s = __ldg(&ei[i]);
        int d = __ldg(&ei[E + i]);
        int p = atomicAdd(&g_cur[layer * NMAX + d], 1);
        g_srclist[(size_t)layer * ECAP + p] = s;
    }
}

// ---------------- aggregation: warp per (node, layer), fp16 gathers, unroll-4 ----------------
__global__ __launch_bounds__(256) void aggregate(int N) {
    const int layer = blockIdx.y;
    const int d = blockIdx.x * 8 + (threadIdx.x >> 5);
    const int lane = threadIdx.x & 31;
    if (d >= N) return;

    const __half* __restrict__ hbase = g_hh + (size_t)layer * NMAX * 128;
    const float* __restrict__ asb = g_as + (size_t)layer * NMAX * 2;
    const float2 adv = __ldg((const float2*)(g_ad + ((size_t)layer * NMAX + d) * 2));
    const float ad0 = adv.x, ad1 = adv.y;

    const float2 asd = __ldg((const float2*)(asb + (size_t)d * 2));
    float w0 = __expf(lrelu(asd.x + ad0));
    float w1 = __expf(lrelu(asd.y + ad1));
    float den0 = w0, den1 = w1;
    float4 hs = h4_to_f4(__ldg((const uint2*)(hbase + (size_t)d * 128) + lane));
    float ws = (lane < 16) ? w0 : w1;
    float4 acc = make_float4(ws * hs.x, ws * hs.y, ws * hs.z, ws * hs.w);

    const int beg = g_off[layer * (NMAX + 1) + d];
    const int end = g_off[layer * (NMAX + 1) + d + 1];
    const int* __restrict__ sl = g_srclist + (size_t)layer * ECAP;

    int e = beg;
    for (; e + 4 <= end; e += 4) {
        int s0 = __ldg(&sl[e]);
        int s1 = __ldg(&sl[e + 1]);
        int s2 = __ldg(&sl[e + 2]);
        int s3 = __ldg(&sl[e + 3]);
        float2 a0 = __ldg((const float2*)(asb + (size_t)s0 * 2));
        float2 a1 = __ldg((const float2*)(asb + (size_t)s1 * 2));
        float2 a2 = __ldg((const float2*)(asb + (size_t)s2 * 2));
        float2 a3 = __ldg((const float2*)(asb + (size_t)s3 * 2));
        uint2 q0 = __ldg((const uint2*)(hbase + (size_t)s0 * 128) + lane);
        uint2 q1 = __ldg((const uint2*)(hbase + (size_t)s1 * 128) + lane);
        uint2 q2 = __ldg((const uint2*)(hbase + (size_t)s2 * 128) + lane);
        uint2 q3 = __ldg((const uint2*)(hbase + (size_t)s3 * 128) + lane);

        float u00 = __expf(lrelu(a0.x + ad0)), u01 = __expf(lrelu(a0.y + ad1));
        float u10 = __expf(lrelu(a1.x + ad0)), u11 = __expf(lrelu(a1.y + ad1));
        float u20 = __expf(lrelu(a2.x + ad0)), u21 = __expf(lrelu(a2.y + ad1));
        float u30 = __expf(lrelu(a3.x + ad0)), u31 = __expf(lrelu(a3.y + ad1));
        den0 += u00 + u10 + u20 + u30;
        den1 += u01 + u11 + u21 + u31;
        float v0 = (lane < 16) ? u00 : u01;
        float v1 = (lane < 16) ? u10 : u11;
        float v2 = (lane < 16) ? u20 : u21;
        float v3 = (lane < 16) ? u30 : u31;
        float4 f0 = h4_to_f4(q0), f1 = h4_to_f4(q1), f2 = h4_to_f4(q2), f3 = h4_to_f4(q3);
        acc.x += v0 * f0.x + v1 * f1.x + v2 * f2.x + v3 * f3.x;
        acc.y += v0 * f0.y + v1 * f1.y + v2 * f2.y + v3 * f3.y;
        acc.z += v0 * f0.z + v1 * f1.z + v2 * f2.z + v3 * f3.z;
        acc.w += v0 * f0.w + v1 * f1.w + v2 * f2.w + v3 * f3.w;
    }
    for (; e < end; e++) {
        int s0 = __ldg(&sl[e]);
        float2 a0 = __ldg((const float2*)(asb + (size_t)s0 * 2));
        uint2 q0 = __ldg((const uint2*)(hbase + (size_t)s0 * 128) + lane);
        float u00 = __expf(lrelu(a0.x + ad0));
        float u01 = __expf(lrelu(a0.y + ad1));
        den0 += u00; den1 += u01;
        float v0 = (lane < 16) ? u00 : u01;
        float4 f0 = h4_to_f4(q0);
        acc.x += v0 * f0.x; acc.y += v0 * f0.y; acc.z += v0 * f0.z; acc.w += v0 * f0.w;
    }

    const float inv = 1.f / ((lane < 16) ? den0 : den1);
    acc.x *= inv; acc.y *= inv; acc.z *= inv; acc.w *= inv;
    *(float4*)(g_out + ((size_t)layer * NMAX + d) * 128 + lane * 4) = acc;
}

// ---------------- final FC (tensor core): y = relu(concat(out0+b1, out1+b2)) @ fcW + fcb ----
// block = 256 thr (8 warps, warp per 16 rows), tile 128 rows x 64 cols, K=256 panels of 16.
__global__ __launch_bounds__(256) void final_gemm_tc(const float* __restrict__ b1,
                                                     const float* __restrict__ b2,
                                                     const float* __restrict__ fcW,
                                                     const float* __restrict__ fcb,
                                                     float* __restrict__ y,
                                                     int N) {
    __shared__ float As[128][20];
    __shared__ float Bs[16][72];
    const int r0 = blockIdx.x * 128;
    const int tid = threadIdx.x;
    const int wid = tid >> 5, lane = tid & 31;
    const int gid = lane >> 2, q = lane & 3;
    const int m0w = wid * 16;

    float c[8][4];
    #pragma unroll
    for (int j = 0; j < 8; j++)
        #pragma unroll
        for (int k = 0; k < 4; k++) c[j][k] = 0.f;

    for (int k0 = 0; k0 < 256; k0 += 16) {
        const int sel = (k0 >= 128);
        const float* __restrict__ bias = sel ? b2 : b1;
        const int kb = k0 - sel * 128;
        const float* __restrict__ src = g_out + (size_t)sel * NMAX * 128;
        // A panel: relu(g_out + bias), 128x16
        #pragma unroll
        for (int i = 0; i < 2; i++) {
            int lin = tid + i * 256;
            int row = lin >> 2, c4 = (lin & 3) * 4;
            float4 v = make_float4(0.f, 0.f, 0.f, 0.f);
            int n = r0 + row;
            if (n < N) {
                float4 g = *(const float4*)&src[(size_t)n * 128 + kb + c4];
                float4 bb = *(const float4*)&bias[kb + c4];
                v.x = fmaxf(g.x + bb.x, 0.f);
                v.y = fmaxf(g.y + bb.y, 0.f);
                v.z = fmaxf(g.z + bb.z, 0.f);
                v.w = fmaxf(g.w + bb.w, 0.f);
            }
            *(float4*)&As[row][c4] = v;
        }
        // B panel: fcW 16x64 (256 float4, 1/thread)
        {
            int kk = tid >> 4, n4 = (tid & 15) * 4;
            *(float4*)&Bs[kk][n4] = *(const float4*)&fcW[(size_t)(k0 + kk) * 64 + n4];
        }
        __syncthreads();

        #pragma unroll
        for (int sub = 0; sub < 2; sub++) {
            const int kk = sub * 8;
            unsigned a[4], b[8][2];
            int m = m0w + gid;
            a[0] = f2tf32(As[m][kk + q]);
            a[1] = f2tf32(As[m + 8][kk + q]);
            a[2] = f2tf32(As[m][kk + q + 4]);
            a[3] = f2tf32(As[m + 8][kk + q + 4]);
            #pragma unroll
            for (int nt = 0; nt < 8; nt++) {
                int n = nt * 8 + gid;
                b[nt][0] = f2tf32(Bs[kk + q][n]);
                b[nt][1] = f2tf32(Bs[kk + q + 4][n]);
            }
            #pragma unroll
            for (int nt = 0; nt < 8; nt++) mma_tf32(c[nt], a, b[nt]);
        }
        __syncthreads();
    }

    #pragma unroll
    for (int nt = 0; nt < 8; nt++) {
        int col = nt * 8 + 2 * q;
        float2 fb = *(const float2*)&fcb[col];
        int r = r0 + m0w + gid;
        if (r < N) {
            float2 v = make_float2(c[nt][0] + fb.x, c[nt][1] + fb.y);
            *(float2*)&y[(size_t)r * 64 + col] = v;
        }
        if (r + 8 < N) {
            float2 v = make_float2(c[nt][2] + fb.x, c[nt][3] + fb.y);
            *(float2*)&y[(size_t)(r + 8) * 64 + col] = v;
        }
    }
}

// ---------------- launcher ----------------
extern "C" void kernel_launch(void* const* d_in, const int* in_sizes, int n_in,
                              void* d_out, int out_size) {
    const float* x    = (const float*)d_in[0];
    const int*   eic  = (const int*)  d_in[1];
    const int*   eil  = (const int*)  d_in[2];
    const float* W1   = (const float*)d_in[3];
    const float* as1  = (const float*)d_in[4];
    const float* ad1  = (const float*)d_in[5];
    const float* b1   = (const float*)d_in[6];
    const float* W2   = (const float*)d_in[7];
    const float* as2  = (const float*)d_in[8];
    const float* ad2  = (const float*)d_in[9];
    const float* b2   = (const float*)d_in[10];
    const float* fcW  = (const float*)d_in[11];
    const float* fcb  = (const float*)d_in[12];
    float* y = (float*)d_out;

    const int N  = in_sizes[0] / 256;
    const int E1 = in_sizes[1] / 2;
    const int E2 = in_sizes[2] / 2;

    zero_deg<<<(2 * NMAX + 255) / 256, 256>>>();

    gemm_h_tc<<<dim3((N + 127) / 128, 2), 256>>>(x, W1, W2, N);

    att_kernel<<<(N + 7) / 8, 256>>>(as1, ad1, as2, ad2, N);

    count_kernel<<<(E1 + 255) / 256, 256>>>(eic, E1, 0);
    count_kernel<<<(E2 + 255) / 256, 256>>>(eil, E2, 1);
    scan_kernel<<<2, 1024>>>(N);
    scatter_kernel<<<(E1 + 255) / 256, 256>>>(eic, E1, 0);
    scatter_kernel<<<(E2 + 255) / 256, 256>>>(eil, E2, 1);

    aggregate<<<dim3((N + 7) / 8, 2), 256>>>(N);

    final_gemm_tc<<<(N + 127) / 128, 256>>>(b1, b2, fcW, fcb, y, N);
}

// round 15
// speedup vs baseline: 1.9726x; 1.0240x over previous
#include <cuda_runtime.h>
#include <cuda_fp16.h>
#include <cuda_bf16.h>
#include <cstdint>

#define NMAX 100000
#define ECAP 1700000
#define NEG_SLOPE 0.2f

// ---------------- scratch (device globals; no allocation allowed) ----------------
__device__ __half g_hh[(size_t)2 * NMAX * 128];      // [layer][node][128] fp16 features
__device__ float  g_as[(size_t)2 * NMAX * 2];        // [layer][node][head] a_src logits
__device__ float  g_ad[(size_t)2 * NMAX * 2];        // [layer][node][head] a_dst logits
__device__ float  g_out[(size_t)2 * NMAX * 128];     // [layer][node][128] normalized aggregates
__device__ int    g_deg[2 * NMAX];
__device__ int    g_off[2 * (NMAX + 1)];
__device__ int    g_cur[2 * NMAX];
__device__ int    g_srclist[(size_t)2 * ECAP];

__device__ __forceinline__ float4 h4_to_f4(uint2 u) {
    __half2 a = *(__half2*)&u.x;
    __half2 b = *(__half2*)&u.y;
    float2 fa = __half22float2(a), fb = __half22float2(b);
    return make_float4(fa.x, fa.y, fb.x, fb.y);
}
__device__ __forceinline__ float lrelu(float v) { return v > 0.f ? v : NEG_SLOPE * v; }
__device__ __forceinline__ unsigned f2tf32(float f) {
    unsigned r;
    asm("cvt.rna.tf32.f32 %0, %1;" : "=r"(r) : "f"(f));
    return r;
}
__device__ __forceinline__ void mma_tf32(float* c, const unsigned* a, const unsigned* b) {
    asm volatile(
        "mma.sync.aligned.m16n8k8.row.col.f32.tf32.tf32.f32 "
        "{%0,%1,%2,%3}, {%4,%5,%6,%7}, {%8,%9}, {%0,%1,%2,%3};"
        : "+f"(c[0]), "+f"(c[1]), "+f"(c[2]), "+f"(c[3])
        : "r"(a[0]), "r"(a[1]), "r"(a[2]), "r"(a[3]), "r"(b[0]), "r"(b[1]));
}

// ---------------- zero degree counters ----------------
__global__ void zero_deg() {
    int i = blockIdx.x * blockDim.x + threadIdx.x;
    if (i < 2 * NMAX) g_deg[i] = 0;
}

// ---------------- tensor-core GEMM: h = x @ W(layer) -> fp16 g_hh ----------------
__global__ __launch_bounds__(256) void gemm_h_tc(const float* __restrict__ x,
                                                 const float* __restrict__ W1,
                                                 const float* __restrict__ W2,
                                                 int N) {
    __shared__ float As[128][20];
    __shared__ float Bs[16][136];
    const int layer = blockIdx.y;
    const float* __restrict__ W = layer ? W2 : W1;
    const int r0 = blockIdx.x * 128;
    const int tid = threadIdx.x;
    const int wid = tid >> 5, lane = tid & 31;
    const int gid = lane >> 2, q = lane & 3;
    const int m0w = (wid & 3) * 32;
    const int n0w = (wid >> 2) * 64;

    float c[2][8][4];
    #pragma unroll
    for (int i = 0; i < 2; i++)
        #pragma unroll
        for (int j = 0; j < 8; j++)
            #pragma unroll
            for (int k = 0; k < 4; k++) c[i][j][k] = 0.f;

    for (int k0 = 0; k0 < 256; k0 += 16) {
        #pragma unroll
        for (int i = 0; i < 2; i++) {
            int lin = tid + i * 256;
            int row = lin >> 2, c4 = (lin & 3) * 4;
            float4 v = make_float4(0.f, 0.f, 0.f, 0.f);
            int n = r0 + row;
            if (n < N) v = *(const float4*)&x[(size_t)n * 256 + k0 + c4];
            *(float4*)&As[row][c4] = v;
        }
        #pragma unroll
        for (int i = 0; i < 2; i++) {
            int lin = tid + i * 256;
            int kk = lin >> 5, n4 = (lin & 31) * 4;
            *(float4*)&Bs[kk][n4] = *(const float4*)&W[(size_t)(k0 + kk) * 128 + n4];
        }
        __syncthreads();

        #pragma unroll
        for (int sub = 0; sub < 2; sub++) {
            const int kk = sub * 8;
            unsigned a[2][4], b[8][2];
            #pragma unroll
            for (int mt = 0; mt < 2; mt++) {
                int m = m0w + mt * 16 + gid;
                a[mt][0] = f2tf32(As[m][kk + q]);
                a[mt][1] = f2tf32(As[m + 8][kk + q]);
                a[mt][2] = f2tf32(As[m][kk + q + 4]);
                a[mt][3] = f2tf32(As[m + 8][kk + q + 4]);
            }
            #pragma unroll
            for (int nt = 0; nt < 8; nt++) {
                int n = n0w + nt * 8 + gid;
                b[nt][0] = f2tf32(Bs[kk + q][n]);
                b[nt][1] = f2tf32(Bs[kk + q + 4][n]);
            }
            #pragma unroll
            for (int mt = 0; mt < 2; mt++)
                #pragma unroll
                for (int nt = 0; nt < 8; nt++) mma_tf32(c[mt][nt], a[mt], b[nt]);
        }
        __syncthreads();
    }

    __half* __restrict__ hb = g_hh + (size_t)layer * NMAX * 128;
    #pragma unroll
    for (int mt = 0; mt < 2; mt++) {
        #pragma unroll
        for (int nt = 0; nt < 8; nt++) {
            int col = n0w + nt * 8 + 2 * q;
            int r = r0 + m0w + mt * 16 + gid;
            if (r < N) {
                __half2 p = __floats2half2_rn(c[mt][nt][0], c[mt][nt][1]);
                *(__half2*)(hb + (size_t)r * 128 + col) = p;
            }
            if (r + 8 < N) {
                __half2 p = __floats2half2_rn(c[mt][nt][2], c[mt][nt][3]);
                *(__half2*)(hb + (size_t)(r + 8) * 128 + col) = p;
            }
        }
    }
}

// ---------------- per-node attention logits (warp per node, fp16 h) ----------------
__global__ __launch_bounds__(256) void att_kernel(const float* __restrict__ as1,
                                                  const float* __restrict__ ad1,
                                                  const float* __restrict__ as2,
                                                  const float* __restrict__ ad2,
                                                  int N) {
    int w = (int)(((size_t)blockIdx.x * blockDim.x + threadIdx.x) >> 5);
    int lane = threadIdx.x & 31;
    if (w >= N) return;
    const int p0 = lane * 4;
    #pragma unroll
    for (int l = 0; l < 2; l++) {
        const float* __restrict__ pa = l ? as2 : as1;
        const float* __restrict__ pd = l ? ad2 : ad1;
        uint2 qv = __ldg((const uint2*)(g_hh + ((size_t)l * NMAX + w) * 128) + lane);
        float4 f = h4_to_f4(qv);
        float ss = f.x * pa[p0] + f.y * pa[p0 + 1] + f.z * pa[p0 + 2] + f.w * pa[p0 + 3];
        float sd = f.x * pd[p0] + f.y * pd[p0 + 1] + f.z * pd[p0 + 2] + f.w * pd[p0 + 3];
        #pragma unroll
        for (int off = 8; off; off >>= 1) {
            ss += __shfl_down_sync(0xffffffffu, ss, off, 16);
            sd += __shfl_down_sync(0xffffffffu, sd, off, 16);
        }
        if ((lane & 15) == 0) {
            int head = lane >> 4;
            g_as[((size_t)l * NMAX + w) * 2 + head] = ss;
            g_ad[((size_t)l * NMAX + w) * 2 + head] = sd;
        }
    }
}

// ---------------- CSR build (int4-vectorized: 4 edges/thread) ----------------
__global__ __launch_bounds__(256) void count_kernel(const int* __restrict__ ei, int E, int layer) {
    int i = (blockIdx.x * blockDim.x + threadIdx.x) * 4;
    if (i >= E) return;
    int* deg = g_deg + layer * NMAX;
    if ((E & 3) == 0 && i + 4 <= E) {
        int4 d4 = __ldg((const int4*)&ei[E + i]);
        atomicAdd(&deg[d4.x], 1);
        atomicAdd(&deg[d4.y], 1);
        atomicAdd(&deg[d4.z], 1);
        atomicAdd(&deg[d4.w], 1);
    } else {
        int hi = min(i + 4, E);
        for (int j = i; j < hi; j++) atomicAdd(&deg[__ldg(&ei[E + j])], 1);
    }
}

__global__ __launch_bounds__(1024) void scan_kernel(int N) {
    const int layer = blockIdx.x;
    const int* deg = g_deg + layer * NMAX;
    int* off = g_off + layer * (NMAX + 1);
    int* cur = g_cur + layer * NMAX;
    __shared__ int sh[1024];
    const int tid = threadIdx.x;
    const int chunk = (N + 1023) >> 10;
    const int lo = tid * chunk;
    const int hi = min(lo + chunk, N);
    int s = 0;
    for (int i = lo; i < hi; i++) s += deg[i];
    sh[tid] = s;
    __syncthreads();
    for (int o = 1; o < 1024; o <<= 1) {
        int v = sh[tid];
        int add = (tid >= o) ? sh[tid - o] : 0;
        __syncthreads();
        sh[tid] = v + add;
        __syncthreads();
    }
    int run = (tid == 0) ? 0 : sh[tid - 1];
    for (int i = lo; i < hi; i++) {
        off[i] = run;
        cur[i] = run;
        run += deg[i];
    }
    if (tid == 1023) off[N] = sh[1023];
}

__global__ __launch_bounds__(256) void scatter_kernel(const int* __restrict__ ei, int E, int layer) {
    int i = (blockIdx.x * blockDim.x + threadIdx.x) * 4;
    if (i >= E) return;
    int* cur = g_cur + layer * NMAX;
    int* sl = g_srclist + (size_t)layer * ECAP;
    if ((E & 3) == 0 && i + 4 <= E) {
        int4 s4 = __ldg((const int4*)&ei[i]);
        int4 d4 = __ldg((const int4*)&ei[E + i]);
        sl[atomicAdd(&cur[d4.x], 1)] = s4.x;
        sl[atomicAdd(&cur[d4.y], 1)] = s4.y;
        sl[atomicAdd(&cur[d4.z], 1)] = s4.z;
        sl[atomicAdd(&cur[d4.w], 1)] = s4.w;
    } else {
        int hi = min(i + 4, E);
        for (int j = i; j < hi; j++) {
            int s = __ldg(&ei[j]);
            int d = __ldg(&ei[E + j]);
            sl[atomicAdd(&cur[d], 1)] = s;
        }
    }
}

// ---------------- aggregation: warp per (node, layer), edge-pair lanes ----------------
// Lanes 0-15 process even edges, 16-31 odd edges; each lane loads uint4 = 8 halves
// (its 8 output columns). Self-loop is virtual edge index `cnt`. Final shfl_xor(16)
// merges the two edge subsets for both acc and den.
__global__ __launch_bounds__(256) void aggregate(int N) {
    const int layer = blockIdx.y;
    const int d = blockIdx.x * 8 + (threadIdx.x >> 5);
    const int lane = threadIdx.x & 31;
    if (d >= N) return;

    const __half* __restrict__ hbase = g_hh + (size_t)layer * NMAX * 128;
    const float* __restrict__ asb = g_as + (size_t)layer * NMAX * 2;
    const float2 adv = __ldg((const float2*)(g_ad + ((size_t)layer * NMAX + d) * 2));
    const float ad0 = adv.x, ad1 = adv.y;

    const int beg = g_off[layer * (NMAX + 1) + d];
    const int cnt = g_off[layer * (NMAX + 1) + d + 1] - beg;
    const int T = cnt + 1;                       // + self loop
    const int* __restrict__ sl = g_srclist + (size_t)layer * ECAP + beg;

    const int sub = lane >> 4;                   // 0: even edge, 1: odd edge
    const int l16 = lane & 15;                   // covers cols 8*l16 .. 8*l16+7
    const int head1 = (l16 >= 8);                // this lane's columns' head

    float acc[8] = {0.f, 0.f, 0.f, 0.f, 0.f, 0.f, 0.f, 0.f};
    float den = 0.f;                             // lane's head, lane's edge subset

    int i = 0;
    // unrolled: 2 pairs (4 edges) per iteration
    for (; i + 4 <= T; i += 4) {
        int sA0 = (i     < cnt) ? __ldg(&sl[i])     : d;
        int sA1 = (i + 1 < cnt) ? __ldg(&sl[i + 1]) : d;
        int sB0 = (i + 2 < cnt) ? __ldg(&sl[i + 2]) : d;
        int sB1 = (i + 3 < cnt) ? __ldg(&sl[i + 3]) : d;
        int sA = sub ? sA1 : sA0;
        int sB = sub ? sB1 : sB0;
        float2 aA = __ldg((const float2*)(asb + (size_t)sA * 2));
        float2 aB = __ldg((const float2*)(asb + (size_t)sB * 2));
        uint4 qA = __ldg((const uint4*)(hbase + (size_t)sA * 128 + l16 * 8));
        uint4 qB = __ldg((const uint4*)(hbase + (size_t)sB * 128 + l16 * 8));

        float uA0 = __expf(lrelu(aA.x + ad0)), uA1 = __expf(lrelu(aA.y + ad1));
        float uB0 = __expf(lrelu(aB.x + ad0)), uB1 = __expf(lrelu(aB.y + ad1));
        float uA = head1 ? uA1 : uA0;
        float uB = head1 ? uB1 : uB0;
        den += uA + uB;
        const __half2* hA = (const __half2*)&qA;
        const __half2* hB = (const __half2*)&qB;
        #pragma unroll
        for (int j = 0; j < 4; j++) {
            float2 fA = __half22float2(hA[j]);
            float2 fB = __half22float2(hB[j]);
            acc[2 * j]     += uA * fA.x + uB * fB.x;
            acc[2 * j + 1] += uA * fA.y + uB * fB.y;
        }
    }
    // one remaining pair
    if (i + 2 <= T) {
        int s0 = (i     < cnt) ? __ldg(&sl[i])     : d;
        int s1 = (i + 1 < cnt) ? __ldg(&sl[i + 1]) : d;
        int s = sub ? s1 : s0;
        float2 a = __ldg((const float2*)(asb + (size_t)s * 2));
        uint4 qv = __ldg((const uint4*)(hbase + (size_t)s * 128 + l16 * 8));
        float u0 = __expf(lrelu(a.x + ad0)), u1 = __expf(lrelu(a.y + ad1));
        float u = head1 ? u1 : u0;
        den += u;
        const __half2* hq = (const __half2*)&qv;
        #pragma unroll
        for (int j = 0; j < 4; j++) {
            float2 f = __half22float2(hq[j]);
            acc[2 * j]     += u * f.x;
            acc[2 * j + 1] += u * f.y;
        }
        i += 2;
    }
    // single tail (low half-warp only)
    if (i < T) {
        int s = (i < cnt) ? __ldg(&sl[i]) : d;
        float2 a = __ldg((const float2*)(asb + (size_t)s * 2));
        uint4 qv = __ldg((const uint4*)(hbase + (size_t)s * 128 + l16 * 8));
        float u0 = __expf(lrelu(a.x + ad0)), u1 = __expf(lrelu(a.y + ad1));
        float u = head1 ? u1 : u0;
        if (sub) u = 0.f;
        den += u;
        const __half2* hq = (const __half2*)&qv;
        #pragma unroll
        for (int j = 0; j < 4; j++) {
            float2 f = __half22float2(hq[j]);
            acc[2 * j]     += u * f.x;
            acc[2 * j + 1] += u * f.y;
        }
    }

    // merge even/odd edge subsets
    #pragma unroll
    for (int j = 0; j < 8; j++) acc[j] += __shfl_xor_sync(0xffffffffu, acc[j], 16);
    den += __shfl_xor_sync(0xffffffffu, den, 16);

    const float inv = 1.f / den;
    float* outp = g_out + ((size_t)layer * NMAX + d) * 128 + l16 * 8 + sub * 4;
    float4 v;
    if (sub) v = make_float4(acc[4] * inv, acc[5] * inv, acc[6] * inv, acc[7] * inv);
    else     v = make_float4(acc[0] * inv, acc[1] * inv, acc[2] * inv, acc[3] * inv);
    *(float4*)outp = v;
}

// ---------------- final FC (tensor core) ----------------
__global__ __launch_bounds__(256) void final_gemm_tc(const float* __restrict__ b1,
                                                     const float* __restrict__ b2,
                                                     const float* __restrict__ fcW,
                                                     const float* __restrict__ fcb,
                                                     float* __restrict__ y,
                                                     int N) {
    __shared__ float As[128][20];
    __shared__ float Bs[16][72];
    const int r0 = blockIdx.x * 128;
    const int tid = threadIdx.x;
    const int wid = tid >> 5, lane = tid & 31;
    const int gid = lane >> 2, q = lane & 3;
    const int m0w = wid * 16;

    float c[8][4];
    #pragma unroll
    for (int j = 0; j < 8; j++)
        #pragma unroll
        for (int k = 0; k < 4; k++) c[j][k] = 0.f;

    for (int k0 = 0; k0 < 256; k0 += 16) {
        const int sel = (k0 >= 128);
        const float* __restrict__ bias = sel ? b2 : b1;
        const int kb = k0 - sel * 128;
        const float* __restrict__ src = g_out + (size_t)sel * NMAX * 128;
        #pragma unroll
        for (int i = 0; i < 2; i++) {
            int lin = tid + i * 256;
            int row = lin >> 2, c4 = (lin & 3) * 4;
            float4 v = make_float4(0.f, 0.f, 0.f, 0.f);
            int n = r0 + row;
            if (n < N) {
                float4 g = *(const float4*)&src[(size_t)n * 128 + kb + c4];
                float4 bb = *(const float4*)&bias[kb + c4];
                v.x = fmaxf(g.x + bb.x, 0.f);
                v.y = fmaxf(g.y + bb.y, 0.f);
                v.z = fmaxf(g.z + bb.z, 0.f);
                v.w = fmaxf(g.w + bb.w, 0.f);
            }
            *(float4*)&As[row][c4] = v;
        }
        {
            int kk = tid >> 4, n4 = (tid & 15) * 4;
            *(float4*)&Bs[kk][n4] = *(const float4*)&fcW[(size_t)(k0 + kk) * 64 + n4];
        }
        __syncthreads();

        #pragma unroll
        for (int sub = 0; sub < 2; sub++) {
            const int kk = sub * 8;
            unsigned a[4], b[8][2];
            int m = m0w + gid;
            a[0] = f2tf32(As[m][kk + q]);
            a[1] = f2tf32(As[m + 8][kk + q]);
            a[2] = f2tf32(As[m][kk + q + 4]);
            a[3] = f2tf32(As[m + 8][kk + q + 4]);
            #pragma unroll
            for (int nt = 0; nt < 8; nt++) {
                int n = nt * 8 + gid;
                b[nt][0] = f2tf32(Bs[kk + q][n]);
                b[nt][1] = f2tf32(Bs[kk + q + 4][n]);
            }
            #pragma unroll
            for (int nt = 0; nt < 8; nt++) mma_tf32(c[nt], a, b[nt]);
        }
        __syncthreads();
    }

    #pragma unroll
    for (int nt = 0; nt < 8; nt++) {
        int col = nt * 8 + 2 * q;
        float2 fb = *(const float2*)&fcb[col];
        int r = r0 + m0w + gid;
        if (r < N) {
            float2 v = make_float2(c[nt][0] + fb.x, c[nt][1] + fb.y);
            *(float2*)&y[(size_t)r * 64 + col] = v;
        }
        if (r + 8 < N) {
            float2 v = make_float2(c[nt][2] + fb.x, c[nt][3] + fb.y);
            *(float2*)&y[(size_t)(r + 8) * 64 + col] = v;
        }
    }
}

// ---------------- launcher ----------------
extern "C" void kernel_launch(void* const* d_in, const int* in_sizes, int n_in,
                              void* d_out, int out_size) {
    const float* x    = (const float*)d_in[0];
    const int*   eic  = (const int*)  d_in[1];
    const int*   eil  = (const int*)  d_in[2];
    const float* W1   = (const float*)d_in[3];
    const float* as1  = (const float*)d_in[4];
    const float* ad1  = (const float*)d_in[5];
    const float* b1   = (const float*)d_in[6];
    const float* W2   = (const float*)d_in[7];
    const float* as2  = (const float*)d_in[8];
    const float* ad2  = (const float*)d_in[9];
    const float* b2   = (const float*)d_in[10];
    const float* fcW  = (const float*)d_in[11];
    const float* fcb  = (const float*)d_in[12];
    float* y = (float*)d_out;

    const int N  = in_sizes[0] / 256;
    const int E1 = in_sizes[1] / 2;
    const int E2 = in_sizes[2] / 2;

    zero_deg<<<(2 * NMAX + 255) / 256, 256>>>();

    gemm_h_tc<<<dim3((N + 127) / 128, 2), 256>>>(x, W1, W2, N);

    att_kernel<<<(N + 7) / 8, 256>>>(as1, ad1, as2, ad2, N);

    count_kernel<<<(E1 / 4 + 255) / 256 + 1, 256>>>(eic, E1, 0);
    count_kernel<<<(E2 / 4 + 255) / 256 + 1, 256>>>(eil, E2, 1);
    scan_kernel<<<2, 1024>>>(N);
    scatter_kernel<<<(E1 / 4 + 255) / 256 + 1, 256>>>(eic, E1, 0);
    scatter_kernel<<<(E2 / 4 + 255) / 256 + 1, 256>>>(eil, E2, 1);

    aggregate<<<dim3((N + 7) / 8, 2), 256>>>(N);

    final_gemm_tc<<<(N + 127) / 128, 256>>>(b1, b2, fcW, fcb, y, N);
}

// round 16
// speedup vs baseline: 2.2157x; 1.1232x over previous
#include <cuda_runtime.h>
#include <cuda_fp16.h>
#include <cuda_bf16.h>
#include <cstdint>

#define NMAX 100000
#define ECAP 1700000
#define NEG_SLOPE 0.2f

// ---------------- scratch (device globals; no allocation allowed) ----------------
__device__ __half g_hh[(size_t)2 * NMAX * 128];      // [layer][node][128] fp16 features
__device__ float  g_as[(size_t)2 * NMAX * 2];        // [layer][node][head] a_src logits
__device__ float  g_ad[(size_t)2 * NMAX * 2];        // [layer][node][head] a_dst logits
__device__ float  g_out[(size_t)2 * NMAX * 128];     // [layer][node][128] normalized aggregates
__device__ int    g_deg[2 * NMAX];
__device__ int    g_off[2 * (NMAX + 1)];
__device__ int    g_cur[2 * NMAX];
__device__ int    g_srclist[(size_t)2 * ECAP];

__device__ __forceinline__ float4 h4_to_f4(uint2 u) {
    __half2 a = *(__half2*)&u.x;
    __half2 b = *(__half2*)&u.y;
    float2 fa = __half22float2(a), fb = __half22float2(b);
    return make_float4(fa.x, fa.y, fb.x, fb.y);
}
__device__ __forceinline__ float lrelu(float v) { return v > 0.f ? v : NEG_SLOPE * v; }
__device__ __forceinline__ unsigned f2tf32(float f) {
    unsigned r;
    asm("cvt.rna.tf32.f32 %0, %1;" : "=r"(r) : "f"(f));
    return r;
}
__device__ __forceinline__ void mma_tf32(float* c, const unsigned* a, const unsigned* b) {
    asm volatile(
        "mma.sync.aligned.m16n8k8.row.col.f32.tf32.tf32.f32 "
        "{%0,%1,%2,%3}, {%4,%5,%6,%7}, {%8,%9}, {%0,%1,%2,%3};"
        : "+f"(c[0]), "+f"(c[1]), "+f"(c[2]), "+f"(c[3])
        : "r"(a[0]), "r"(a[1]), "r"(a[2]), "r"(a[3]), "r"(b[0]), "r"(b[1]));
}

// ---------------- zero degree counters ----------------
__global__ void zero_deg() {
    int i = blockIdx.x * blockDim.x + threadIdx.x;
    if (i < 2 * NMAX) g_deg[i] = 0;
}

// ---------------- tensor-core GEMM: h = x @ W(layer) -> fp16 g_hh ----------------
// smem holds pre-converted tf32 bits (cvt once per element at panel load).
__global__ __launch_bounds__(256) void gemm_h_tc(const float* __restrict__ x,
                                                 const float* __restrict__ W1,
                                                 const float* __restrict__ W2,
                                                 int N) {
    __shared__ unsigned As[128][20];
    __shared__ unsigned Bs[16][136];
    const int layer = blockIdx.y;
    const float* __restrict__ W = layer ? W2 : W1;
    const int r0 = blockIdx.x * 128;
    const int tid = threadIdx.x;
    const int wid = tid >> 5, lane = tid & 31;
    const int gid = lane >> 2, q = lane & 3;
    const int m0w = (wid & 3) * 32;
    const int n0w = (wid >> 2) * 64;

    float c[2][8][4];
    #pragma unroll
    for (int i = 0; i < 2; i++)
        #pragma unroll
        for (int j = 0; j < 8; j++)
            #pragma unroll
            for (int k = 0; k < 4; k++) c[i][j][k] = 0.f;

    for (int k0 = 0; k0 < 256; k0 += 16) {
        #pragma unroll
        for (int i = 0; i < 2; i++) {
            int lin = tid + i * 256;
            int row = lin >> 2, c4 = (lin & 3) * 4;
            float4 v = make_float4(0.f, 0.f, 0.f, 0.f);
            int n = r0 + row;
            if (n < N) v = *(const float4*)&x[(size_t)n * 256 + k0 + c4];
            uint4 u = make_uint4(f2tf32(v.x), f2tf32(v.y), f2tf32(v.z), f2tf32(v.w));
            *(uint4*)&As[row][c4] = u;
        }
        #pragma unroll
        for (int i = 0; i < 2; i++) {
            int lin = tid + i * 256;
            int kk = lin >> 5, n4 = (lin & 31) * 4;
            float4 v = *(const float4*)&W[(size_t)(k0 + kk) * 128 + n4];
            uint4 u = make_uint4(f2tf32(v.x), f2tf32(v.y), f2tf32(v.z), f2tf32(v.w));
            *(uint4*)&Bs[kk][n4] = u;
        }
        __syncthreads();

        #pragma unroll
        for (int sub = 0; sub < 2; sub++) {
            const int kk = sub * 8;
            unsigned a[2][4], b[8][2];
            #pragma unroll
            for (int mt = 0; mt < 2; mt++) {
                int m = m0w + mt * 16 + gid;
                a[mt][0] = As[m][kk + q];
                a[mt][1] = As[m + 8][kk + q];
                a[mt][2] = As[m][kk + q + 4];
                a[mt][3] = As[m + 8][kk + q + 4];
            }
            #pragma unroll
            for (int nt = 0; nt < 8; nt++) {
                int n = n0w + nt * 8 + gid;
                b[nt][0] = Bs[kk + q][n];
                b[nt][1] = Bs[kk + q + 4][n];
            }
            #pragma unroll
            for (int mt = 0; mt < 2; mt++)
                #pragma unroll
                for (int nt = 0; nt < 8; nt++) mma_tf32(c[mt][nt], a[mt], b[nt]);
        }
        __syncthreads();
    }

    __half* __restrict__ hb = g_hh + (size_t)layer * NMAX * 128;
    #pragma unroll
    for (int mt = 0; mt < 2; mt++) {
        #pragma unroll
        for (int nt = 0; nt < 8; nt++) {
            int col = n0w + nt * 8 + 2 * q;
            int r = r0 + m0w + mt * 16 + gid;
            if (r < N) {
                __half2 p = __floats2half2_rn(c[mt][nt][0], c[mt][nt][1]);
                *(__half2*)(hb + (size_t)r * 128 + col) = p;
            }
            if (r + 8 < N) {
                __half2 p = __floats2half2_rn(c[mt][nt][2], c[mt][nt][3]);
                *(__half2*)(hb + (size_t)(r + 8) * 128 + col) = p;
            }
        }
    }
}

// ---------------- per-node attention logits (warp per node, fp16 h) ----------------
__global__ __launch_bounds__(256) void att_kernel(const float* __restrict__ as1,
                                                  const float* __restrict__ ad1,
                                                  const float* __restrict__ as2,
                                                  const float* __restrict__ ad2,
                                                  int N) {
    int w = (int)(((size_t)blockIdx.x * blockDim.x + threadIdx.x) >> 5);
    int lane = threadIdx.x & 31;
    if (w >= N) return;
    const int p0 = lane * 4;
    #pragma unroll
    for (int l = 0; l < 2; l++) {
        const float* __restrict__ pa = l ? as2 : as1;
        const float* __restrict__ pd = l ? ad2 : ad1;
        uint2 qv = __ldg((const uint2*)(g_hh + ((size_t)l * NMAX + w) * 128) + lane);
        float4 f = h4_to_f4(qv);
        float ss = f.x * pa[p0] + f.y * pa[p0 + 1] + f.z * pa[p0 + 2] + f.w * pa[p0 + 3];
        float sd = f.x * pd[p0] + f.y * pd[p0 + 1] + f.z * pd[p0 + 2] + f.w * pd[p0 + 3];
        #pragma unroll
        for (int off = 8; off; off >>= 1) {
            ss += __shfl_down_sync(0xffffffffu, ss, off, 16);
            sd += __shfl_down_sync(0xffffffffu, sd, off, 16);
        }
        if ((lane & 15) == 0) {
            int head = lane >> 4;
            g_as[((size_t)l * NMAX + w) * 2 + head] = ss;
            g_ad[((size_t)l * NMAX + w) * 2 + head] = sd;
        }
    }
}

// ---------------- CSR build (int4-vectorized: 4 edges/thread) ----------------
__global__ __launch_bounds__(256) void count_kernel(const int* __restrict__ ei, int E, int layer) {
    int i = (blockIdx.x * blockDim.x + threadIdx.x) * 4;
    if (i >= E) return;
    int* deg = g_deg + layer * NMAX;
    if ((E & 3) == 0 && i + 4 <= E) {
        int4 d4 = __ldg((const int4*)&ei[E + i]);
        atomicAdd(&deg[d4.x], 1);
        atomicAdd(&deg[d4.y], 1);
        atomicAdd(&deg[d4.z], 1);
        atomicAdd(&deg[d4.w], 1);
    } else {
        int hi = min(i + 4, E);
        for (int j = i; j < hi; j++) atomicAdd(&deg[__ldg(&ei[E + j])], 1);
    }
}

__global__ __launch_bounds__(1024) void scan_kernel(int N) {
    const int layer = blockIdx.x;
    const int* deg = g_deg + layer * NMAX;
    int* off = g_off + layer * (NMAX + 1);
    int* cur = g_cur + layer * NMAX;
    __shared__ int sh[1024];
    const int tid = threadIdx.x;
    const int chunk = (N + 1023) >> 10;
    const int lo = tid * chunk;
    const int hi = min(lo + chunk, N);
    int s = 0;
    for (int i = lo; i < hi; i++) s += deg[i];
    sh[tid] = s;
    __syncthreads();
    for (int o = 1; o < 1024; o <<= 1) {
        int v = sh[tid];
        int add = (tid >= o) ? sh[tid - o] : 0;
        __syncthreads();
        sh[tid] = v + add;
        __syncthreads();
    }
    int run = (tid == 0) ? 0 : sh[tid - 1];
    for (int i = lo; i < hi; i++) {
        off[i] = run;
        cur[i] = run;
        run += deg[i];
    }
    if (tid == 1023) off[N] = sh[1023];
}

__global__ __launch_bounds__(256) void scatter_kernel(const int* __restrict__ ei, int E, int layer) {
    int i = (blockIdx.x * blockDim.x + threadIdx.x) * 4;
    if (i >= E) return;
    int* cur = g_cur + layer * NMAX;
    int* sl = g_srclist + (size_t)layer * ECAP;
    if ((E & 3) == 0 && i + 4 <= E) {
        int4 s4 = __ldg((const int4*)&ei[i]);
        int4 d4 = __ldg((const int4*)&ei[E + i]);
        sl[atomicAdd(&cur[d4.x], 1)] = s4.x;
        sl[atomicAdd(&cur[d4.y], 1)] = s4.y;
        sl[atomicAdd(&cur[d4.z], 1)] = s4.z;
        sl[atomicAdd(&cur[d4.w], 1)] = s4.w;
    } else {
        int hi = min(i + 4, E);
        for (int j = i; j < hi; j++) {
            int s = __ldg(&ei[j]);
            int d = __ldg(&ei[E + j]);
            sl[atomicAdd(&cur[d], 1)] = s;
        }
    }
}

// ---------------- aggregation: warp per (node, layer), edge-pair lanes ----------------
__global__ __launch_bounds__(256) void aggregate(int N) {
    const int layer = blockIdx.y;
    const int d = blockIdx.x * 8 + (threadIdx.x >> 5);
    const int lane = threadIdx.x & 31;
    if (d >= N) return;

    const __half* __restrict__ hbase = g_hh + (size_t)layer * NMAX * 128;
    const float* __restrict__ asb = g_as + (size_t)layer * NMAX * 2;
    const float2 adv = __ldg((const float2*)(g_ad + ((size_t)layer * NMAX + d) * 2));
    const float ad0 = adv.x, ad1 = adv.y;

    const int beg = g_off[layer * (NMAX + 1) + d];
    const int cnt = g_off[layer * (NMAX + 1) + d + 1] - beg;
    const int T = cnt + 1;                       // + self loop
    const int* __restrict__ sl = g_srclist + (size_t)layer * ECAP + beg;

    const int sub = lane >> 4;                   // 0: even edge, 1: odd edge
    const int l16 = lane & 15;                   // covers cols 8*l16 .. 8*l16+7
    const int head1 = (l16 >= 8);

    float acc[8] = {0.f, 0.f, 0.f, 0.f, 0.f, 0.f, 0.f, 0.f};
    float den = 0.f;

    int i = 0;
    for (; i + 4 <= T; i += 4) {
        int sA0 = (i     < cnt) ? __ldg(&sl[i])     : d;
        int sA1 = (i + 1 < cnt) ? __ldg(&sl[i + 1]) : d;
        int sB0 = (i + 2 < cnt) ? __ldg(&sl[i + 2]) : d;
        int sB1 = (i + 3 < cnt) ? __ldg(&sl[i + 3]) : d;
        int sA = sub ? sA1 : sA0;
        int sB = sub ? sB1 : sB0;
        float2 aA = __ldg((const float2*)(asb + (size_t)sA * 2));
        float2 aB = __ldg((const float2*)(asb + (size_t)sB * 2));
        uint4 qA = __ldg((const uint4*)(hbase + (size_t)sA * 128 + l16 * 8));
        uint4 qB = __ldg((const uint4*)(hbase + (size_t)sB * 128 + l16 * 8));

        float uA0 = __expf(lrelu(aA.x + ad0)), uA1 = __expf(lrelu(aA.y + ad1));
        float uB0 = __expf(lrelu(aB.x + ad0)), uB1 = __expf(lrelu(aB.y + ad1));
        float uA = head1 ? uA1 : uA0;
        float uB = head1 ? uB1 : uB0;
        den += uA + uB;
        const __half2* hA = (const __half2*)&qA;
        const __half2* hB = (const __half2*)&qB;
        #pragma unroll
        for (int j = 0; j < 4; j++) {
            float2 fA = __half22float2(hA[j]);
            float2 fB = __half22float2(hB[j]);
            acc[2 * j]     += uA * fA.x + uB * fB.x;
            acc[2 * j + 1] += uA * fA.y + uB * fB.y;
        }
    }
    if (i + 2 <= T) {
        int s0 = (i     < cnt) ? __ldg(&sl[i])     : d;
        int s1 = (i + 1 < cnt) ? __ldg(&sl[i + 1]) : d;
        int s = sub ? s1 : s0;
        float2 a = __ldg((const float2*)(asb + (size_t)s * 2));
        uint4 qv = __ldg((const uint4*)(hbase + (size_t)s * 128 + l16 * 8));
        float u0 = __expf(lrelu(a.x + ad0)), u1 = __expf(lrelu(a.y + ad1));
        float u = head1 ? u1 : u0;
        den += u;
        const __half2* hq = (const __half2*)&qv;
        #pragma unroll
        for (int j = 0; j < 4; j++) {
            float2 f = __half22float2(hq[j]);
            acc[2 * j]     += u * f.x;
            acc[2 * j + 1] += u * f.y;
        }
        i += 2;
    }
    if (i < T) {
        int s = (i < cnt) ? __ldg(&sl[i]) : d;
        float2 a = __ldg((const float2*)(asb + (size_t)s * 2));
        uint4 qv = __ldg((const uint4*)(hbase + (size_t)s * 128 + l16 * 8));
        float u0 = __expf(lrelu(a.x + ad0)), u1 = __expf(lrelu(a.y + ad1));
        float u = head1 ? u1 : u0;
        if (sub) u = 0.f;
        den += u;
        const __half2* hq = (const __half2*)&qv;
        #pragma unroll
        for (int j = 0; j < 4; j++) {
            float2 f = __half22float2(hq[j]);
            acc[2 * j]     += u * f.x;
            acc[2 * j + 1] += u * f.y;
        }
    }

    #pragma unroll
    for (int j = 0; j < 8; j++) acc[j] += __shfl_xor_sync(0xffffffffu, acc[j], 16);
    den += __shfl_xor_sync(0xffffffffu, den, 16);

    const float inv = 1.f / den;
    float* outp = g_out + ((size_t)layer * NMAX + d) * 128 + l16 * 8 + sub * 4;
    float4 v;
    if (sub) v = make_float4(acc[4] * inv, acc[5] * inv, acc[6] * inv, acc[7] * inv);
    else     v = make_float4(acc[0] * inv, acc[1] * inv, acc[2] * inv, acc[3] * inv);
    *(float4*)outp = v;
}

// ---------------- final FC (tensor core), pre-converted tf32 smem ----------------
__global__ __launch_bounds__(256) void final_gemm_tc(const float* __restrict__ b1,
                                                     const float* __restrict__ b2,
                                                     const float* __restrict__ fcW,
                                                     const float* __restrict__ fcb,
                                                     float* __restrict__ y,
                                                     int N) {
    __shared__ unsigned As[128][20];
    __shared__ unsigned Bs[16][72];
    const int r0 = blockIdx.x * 128;
    const int tid = threadIdx.x;
    const int wid = tid >> 5, lane = tid & 31;
    const int gid = lane >> 2, q = lane & 3;
    const int m0w = wid * 16;

    float c[8][4];
    #pragma unroll
    for (int j = 0; j < 8; j++)
        #pragma unroll
        for (int k = 0; k < 4; k++) c[j][k] = 0.f;

    for (int k0 = 0; k0 < 256; k0 += 16) {
        const int sel = (k0 >= 128);
        const float* __restrict__ bias = sel ? b2 : b1;
        const int kb = k0 - sel * 128;
        const float* __restrict__ src = g_out + (size_t)sel * NMAX * 128;
        #pragma unroll
        for (int i = 0; i < 2; i++) {
            int lin = tid + i * 256;
            int row = lin >> 2, c4 = (lin & 3) * 4;
            float4 v = make_float4(0.f, 0.f, 0.f, 0.f);
            int n = r0 + row;
            if (n < N) {
                float4 g = *(const float4*)&src[(size_t)n * 128 + kb + c4];
                float4 bb = *(const float4*)&bias[kb + c4];
                v.x = fmaxf(g.x + bb.x, 0.f);
                v.y = fmaxf(g.y + bb.y, 0.f);
                v.z = fmaxf(g.z + bb.z, 0.f);
                v.w = fmaxf(g.w + bb.w, 0.f);
            }
            uint4 u = make_uint4(f2tf32(v.x), f2tf32(v.y), f2tf32(v.z), f2tf32(v.w));
            *(uint4*)&As[row][c4] = u;
        }
        {
            int kk = tid >> 4, n4 = (tid & 15) * 4;
            float4 v = *(const float4*)&fcW[(size_t)(k0 + kk) * 64 + n4];
            uint4 u = make_uint4(f2tf32(v.x), f2tf32(v.y), f2tf32(v.z), f2tf32(v.w));
            *(uint4*)&Bs[kk][n4] = u;
        }
        __syncthreads();

        #pragma unroll
        for (int sub = 0; sub < 2; sub++) {
            const int kk = sub * 8;
            unsigned a[4], b[8][2];
            int m = m0w + gid;
            a[0] = As[m][kk + q];
            a[1] = As[m + 8][kk + q];
            a[2] = As[m][kk + q + 4];
            a[3] = As[m + 8][kk + q + 4];
            #pragma unroll
            for (int nt = 0; nt < 8; nt++) {
                int n = nt * 8 + gid;
                b[nt][0] = Bs[kk + q][n];
                b[nt][1] = Bs[kk + q + 4][n];
            }
            #pragma unroll
            for (int nt = 0; nt < 8; nt++) mma_tf32(c[nt], a, b[nt]);
        }
        __syncthreads();
    }

    #pragma unroll
    for (int nt = 0; nt < 8; nt++) {
        int col = nt * 8 + 2 * q;
        float2 fb = *(const float2*)&fcb[col];
        int r = r0 + m0w + gid;
        if (r < N) {
            float2 v = make_float2(c[nt][0] + fb.x, c[nt][1] + fb.y);
            *(float2*)&y[(size_t)r * 64 + col] = v;
        }
        if (r + 8 < N) {
            float2 v = make_float2(c[nt][2] + fb.x, c[nt][3] + fb.y);
            *(float2*)&y[(size_t)(r + 8) * 64 + col] = v;
        }
    }
}

// ---------------- launcher: fork CSR build onto a side stream ----------------
extern "C" void kernel_launch(void* const* d_in, const int* in_sizes, int n_in,
                              void* d_out, int out_size) {
    const float* x    = (const float*)d_in[0];
    const int*   eic  = (const int*)  d_in[1];
    const int*   eil  = (const int*)  d_in[2];
    const float* W1   = (const float*)d_in[3];
    const float* as1  = (const float*)d_in[4];
    const float* ad1  = (const float*)d_in[5];
    const float* b1   = (const float*)d_in[6];
    const float* W2   = (const float*)d_in[7];
    const float* as2  = (const float*)d_in[8];
    const float* ad2  = (const float*)d_in[9];
    const float* b2   = (const float*)d_in[10];
    const float* fcW  = (const float*)d_in[11];
    const float* fcb  = (const float*)d_in[12];
    float* y = (float*)d_out;

    const int N  = in_sizes[0] / 256;
    const int E1 = in_sizes[1] / 2;
    const int E2 = in_sizes[2] / 2;

    // lazily-created side stream + fork/join events (resources only; work per
    // call is identical and fully captured via the event edges)
    static cudaStream_t s2 = nullptr;
    static cudaEvent_t evFork = nullptr, evJoin = nullptr;
    if (s2 == nullptr) {
        cudaStreamCreateWithFlags(&s2, cudaStreamNonBlocking);
        cudaEventCreateWithFlags(&evFork, cudaEventDisableTiming);
        cudaEventCreateWithFlags(&evJoin, cudaEventDisableTiming);
    }

    // fork: CSR build chain on s2, independent of the GEMM path
    cudaEventRecord(evFork, 0);
    cudaStreamWaitEvent(s2, evFork, 0);

    zero_deg<<<(2 * NMAX + 255) / 256, 256, 0, s2>>>();
    count_kernel<<<(E1 / 4 + 255) / 256 + 1, 256, 0, s2>>>(eic, E1, 0);
    count_kernel<<<(E2 / 4 + 255) / 256 + 1, 256, 0, s2>>>(eil, E2, 1);
    scan_kernel<<<2, 1024, 0, s2>>>(N);
    scatter_kernel<<<(E1 / 4 + 255) / 256 + 1, 256, 0, s2>>>(eic, E1, 0);
    scatter_kernel<<<(E2 / 4 + 255) / 256 + 1, 256, 0, s2>>>(eil, E2, 1);
    cudaEventRecord(evJoin, s2);

    // main stream: GEMM -> attention logits (overlaps with CSR build)
    gemm_h_tc<<<dim3((N + 127) / 128, 2), 256>>>(x, W1, W2, N);
    att_kernel<<<(N + 7) / 8, 256>>>(as1, ad1, as2, ad2, N);

    // join, then aggregate + final FC
    cudaStreamWaitEvent(0, evJoin, 0);
    aggregate<<<dim3((N + 7) / 8, 2), 256>>>(N);
    final_gemm_tc<<<(N + 127) / 128, 256>>>(b1, b2, fcW, fcb, y, N);
}

// round 17
// speedup vs baseline: 3.0983x; 1.3984x over previous
#include <cuda_runtime.h>
#include <cuda_fp16.h>
#include <cuda_bf16.h>
#include <cstdint>

#define NMAX 100000
#define ECAP 1700000
#define NEG_SLOPE 0.2f
#define SCAN_CHUNK 1024
#define MAXBLK 128

// ---------------- scratch (device globals; no allocation allowed) ----------------
__device__ __half g_hh[(size_t)2 * NMAX * 128];      // [layer][node][128] fp16 features
__device__ float  g_as[(size_t)2 * NMAX * 2];        // [layer][node][head] a_src logits
__device__ float  g_ad[(size_t)2 * NMAX * 2];        // [layer][node][head] a_dst logits
__device__ float  g_out[(size_t)2 * NMAX * 128];     // [layer][node][128] normalized aggregates
__device__ int    g_deg[2 * NMAX];
__device__ int    g_off[2 * (NMAX + 1)];
__device__ int    g_cur[2 * NMAX];
__device__ int    g_part[2 * MAXBLK];
__device__ int    g_srclist[(size_t)2 * ECAP];

__device__ __forceinline__ float4 h4_to_f4(uint2 u) {
    __half2 a = *(__half2*)&u.x;
    __half2 b = *(__half2*)&u.y;
    float2 fa = __half22float2(a), fb = __half22float2(b);
    return make_float4(fa.x, fa.y, fb.x, fb.y);
}
__device__ __forceinline__ float lrelu(float v) { return v > 0.f ? v : NEG_SLOPE * v; }
__device__ __forceinline__ unsigned f2tf32(float f) {
    unsigned r;
    asm("cvt.rna.tf32.f32 %0, %1;" : "=r"(r) : "f"(f));
    return r;
}
__device__ __forceinline__ void mma_tf32(float* c, const unsigned* a, const unsigned* b) {
    asm volatile(
        "mma.sync.aligned.m16n8k8.row.col.f32.tf32.tf32.f32 "
        "{%0,%1,%2,%3}, {%4,%5,%6,%7}, {%8,%9}, {%0,%1,%2,%3};"
        : "+f"(c[0]), "+f"(c[1]), "+f"(c[2]), "+f"(c[3])
        : "r"(a[0]), "r"(a[1]), "r"(a[2]), "r"(a[3]), "r"(b[0]), "r"(b[1]));
}

// ---------------- zero degree counters ----------------
__global__ void zero_deg() {
    int i = blockIdx.x * blockDim.x + threadIdx.x;
    if (i < 2 * NMAX) g_deg[i] = 0;
}

// ---------------- tensor-core GEMM: h = x @ W(layer) -> fp16 g_hh ----------------
__global__ __launch_bounds__(256) void gemm_h_tc(const float* __restrict__ x,
                                                 const float* __restrict__ W1,
                                                 const float* __restrict__ W2,
                                                 int N) {
    __shared__ unsigned As[128][20];
    __shared__ unsigned Bs[16][136];
    const int layer = blockIdx.y;
    const float* __restrict__ W = layer ? W2 : W1;
    const int r0 = blockIdx.x * 128;
    const int tid = threadIdx.x;
    const int wid = tid >> 5, lane = tid & 31;
    const int gid = lane >> 2, q = lane & 3;
    const int m0w = (wid & 3) * 32;
    const int n0w = (wid >> 2) * 64;

    float c[2][8][4];
    #pragma unroll
    for (int i = 0; i < 2; i++)
        #pragma unroll
        for (int j = 0; j < 8; j++)
            #pragma unroll
            for (int k = 0; k < 4; k++) c[i][j][k] = 0.f;

    for (int k0 = 0; k0 < 256; k0 += 16) {
        #pragma unroll
        for (int i = 0; i < 2; i++) {
            int lin = tid + i * 256;
            int row = lin >> 2, c4 = (lin & 3) * 4;
            float4 v = make_float4(0.f, 0.f, 0.f, 0.f);
            int n = r0 + row;
            if (n < N) v = *(const float4*)&x[(size_t)n * 256 + k0 + c4];
            uint4 u = make_uint4(f2tf32(v.x), f2tf32(v.y), f2tf32(v.z), f2tf32(v.w));
            *(uint4*)&As[row][c4] = u;
        }
        #pragma unroll
        for (int i = 0; i < 2; i++) {
            int lin = tid + i * 256;
            int kk = lin >> 5, n4 = (lin & 31) * 4;
            float4 v = *(const float4*)&W[(size_t)(k0 + kk) * 128 + n4];
            uint4 u = make_uint4(f2tf32(v.x), f2tf32(v.y), f2tf32(v.z), f2tf32(v.w));
            *(uint4*)&Bs[kk][n4] = u;
        }
        __syncthreads();

        #pragma unroll
        for (int sub = 0; sub < 2; sub++) {
            const int kk = sub * 8;
            unsigned a[2][4], b[8][2];
            #pragma unroll
            for (int mt = 0; mt < 2; mt++) {
                int m = m0w + mt * 16 + gid;
                a[mt][0] = As[m][kk + q];
                a[mt][1] = As[m + 8][kk + q];
                a[mt][2] = As[m][kk + q + 4];
                a[mt][3] = As[m + 8][kk + q + 4];
            }
            #pragma unroll
            for (int nt = 0; nt < 8; nt++) {
                int n = n0w + nt * 8 + gid;
                b[nt][0] = Bs[kk + q][n];
                b[nt][1] = Bs[kk + q + 4][n];
            }
            #pragma unroll
            for (int mt = 0; mt < 2; mt++)
                #pragma unroll
                for (int nt = 0; nt < 8; nt++) mma_tf32(c[mt][nt], a[mt], b[nt]);
        }
        __syncthreads();
    }

    __half* __restrict__ hb = g_hh + (size_t)layer * NMAX * 128;
    #pragma unroll
    for (int mt = 0; mt < 2; mt++) {
        #pragma unroll
        for (int nt = 0; nt < 8; nt++) {
            int col = n0w + nt * 8 + 2 * q;
            int r = r0 + m0w + mt * 16 + gid;
            if (r < N) {
                __half2 p = __floats2half2_rn(c[mt][nt][0], c[mt][nt][1]);
                *(__half2*)(hb + (size_t)r * 128 + col) = p;
            }
            if (r + 8 < N) {
                __half2 p = __floats2half2_rn(c[mt][nt][2], c[mt][nt][3]);
                *(__half2*)(hb + (size_t)(r + 8) * 128 + col) = p;
            }
        }
    }
}

// ---------------- per-node attention logits (warp per node, fp16 h) ----------------
__global__ __launch_bounds__(256) void att_kernel(const float* __restrict__ as1,
                                                  const float* __restrict__ ad1,
                                                  const float* __restrict__ as2,
                                                  const float* __restrict__ ad2,
                                                  int N) {
    int w = (int)(((size_t)blockIdx.x * blockDim.x + threadIdx.x) >> 5);
    int lane = threadIdx.x & 31;
    if (w >= N) return;
    const int p0 = lane * 4;
    #pragma unroll
    for (int l = 0; l < 2; l++) {
        const float* __restrict__ pa = l ? as2 : as1;
        const float* __restrict__ pd = l ? ad2 : ad1;
        uint2 qv = __ldg((const uint2*)(g_hh + ((size_t)l * NMAX + w) * 128) + lane);
        float4 f = h4_to_f4(qv);
        float ss = f.x * pa[p0] + f.y * pa[p0 + 1] + f.z * pa[p0 + 2] + f.w * pa[p0 + 3];
        float sd = f.x * pd[p0] + f.y * pd[p0 + 1] + f.z * pd[p0 + 2] + f.w * pd[p0 + 3];
        #pragma unroll
        for (int off = 8; off; off >>= 1) {
            ss += __shfl_down_sync(0xffffffffu, ss, off, 16);
            sd += __shfl_down_sync(0xffffffffu, sd, off, 16);
        }
        if ((lane & 15) == 0) {
            int head = lane >> 4;
            g_as[((size_t)l * NMAX + w) * 2 + head] = ss;
            g_ad[((size_t)l * NMAX + w) * 2 + head] = sd;
        }
    }
}

// ---------------- CSR build (int4-vectorized: 4 edges/thread) ----------------
__global__ __launch_bounds__(256) void count_kernel(const int* __restrict__ ei, int E, int layer) {
    int i = (blockIdx.x * blockDim.x + threadIdx.x) * 4;
    if (i >= E) return;
    int* deg = g_deg + layer * NMAX;
    if ((E & 3) == 0 && i + 4 <= E) {
        int4 d4 = __ldg((const int4*)&ei[E + i]);
        atomicAdd(&deg[d4.x], 1);
        atomicAdd(&deg[d4.y], 1);
        atomicAdd(&deg[d4.z], 1);
        atomicAdd(&deg[d4.w], 1);
    } else {
        int hi = min(i + 4, E);
        for (int j = i; j < hi; j++) atomicAdd(&deg[__ldg(&ei[E + j])], 1);
    }
}

// ---------------- multi-block exclusive scan: partial, tops, final ----------------
__global__ __launch_bounds__(256) void scan_partial(int N) {
    const int layer = blockIdx.y;
    const int* __restrict__ deg = g_deg + layer * NMAX;
    const int tid = threadIdx.x;
    const int lane = tid & 31, wid = tid >> 5;
    int i0 = blockIdx.x * SCAN_CHUNK + tid * 4;
    int s = 0;
    #pragma unroll
    for (int j = 0; j < 4; j++)
        if (i0 + j < N) s += deg[i0 + j];
    #pragma unroll
    for (int o = 16; o; o >>= 1) s += __shfl_xor_sync(0xffffffffu, s, o);
    __shared__ int sw[8];
    if (lane == 0) sw[wid] = s;
    __syncthreads();
    if (tid == 0) {
        int t = 0;
        #pragma unroll
        for (int w = 0; w < 8; w++) t += sw[w];
        g_part[layer * MAXBLK + blockIdx.x] = t;
    }
}

__global__ __launch_bounds__(128) void scan_tops(int nblk, int N) {
    const int layer = blockIdx.x;
    const int tid = threadIdx.x;
    __shared__ int sh[128];
    int v = (tid < nblk) ? g_part[layer * MAXBLK + tid] : 0;
    sh[tid] = v;
    __syncthreads();
    for (int o = 1; o < 128; o <<= 1) {
        int t = sh[tid];
        int add = (tid >= o) ? sh[tid - o] : 0;
        __syncthreads();
        sh[tid] = t + add;
        __syncthreads();
    }
    if (tid < nblk) g_part[layer * MAXBLK + tid] = sh[tid] - v;   // exclusive
    if (tid == 127) g_off[layer * (NMAX + 1) + N] = sh[127];
}

__global__ __launch_bounds__(256) void scan_final(int N) {
    const int layer = blockIdx.y;
    const int* __restrict__ deg = g_deg + layer * NMAX;
    int* __restrict__ off = g_off + layer * (NMAX + 1);
    int* __restrict__ cur = g_cur + layer * NMAX;
    const int tid = threadIdx.x;
    const int lane = tid & 31, wid = tid >> 5;
    int i0 = blockIdx.x * SCAN_CHUNK + tid * 4;
    int d[4];
    #pragma unroll
    for (int j = 0; j < 4; j++) d[j] = (i0 + j < N) ? deg[i0 + j] : 0;
    int s = d[0] + d[1] + d[2] + d[3];
    // warp inclusive scan of thread sums
    int incl = s;
    #pragma unroll
    for (int o = 1; o < 32; o <<= 1) {
        int t = __shfl_up_sync(0xffffffffu, incl, o);
        if (lane >= o) incl += t;
    }
    int wexcl = incl - s;
    __shared__ int sw[8];
    if (lane == 31) sw[wid] = incl;
    __syncthreads();
    int bexcl = 0;
    for (int w = 0; w < wid; w++) bexcl += sw[w];
    int run = g_part[layer * MAXBLK + blockIdx.x] + bexcl + wexcl;
    #pragma unroll
    for (int j = 0; j < 4; j++) {
        if (i0 + j < N) {
            off[i0 + j] = run;
            cur[i0 + j] = run;
            run += d[j];
        }
    }
}

__global__ __launch_bounds__(256) void scatter_kernel(const int* __restrict__ ei, int E, int layer) {
    int i = (blockIdx.x * blockDim.x + threadIdx.x) * 4;
    if (i >= E) return;
    int* cur = g_cur + layer * NMAX;
    int* sl = g_srclist + (size_t)layer * ECAP;
    if ((E & 3) == 0 && i + 4 <= E) {
        int4 s4 = __ldg((const int4*)&ei[i]);
        int4 d4 = __ldg((const int4*)&ei[E + i]);
        sl[atomicAdd(&cur[d4.x], 1)] = s4.x;
        sl[atomicAdd(&cur[d4.y], 1)] = s4.y;
        sl[atomicAdd(&cur[d4.z], 1)] = s4.z;
        sl[atomicAdd(&cur[d4.w], 1)] = s4.w;
    } else {
        int hi = min(i + 4, E);
        for (int j = i; j < hi; j++) {
            int s = __ldg(&ei[j]);
            int d = __ldg(&ei[E + j]);
            sl[atomicAdd(&cur[d], 1)] = s;
        }
    }
}

// ---------------- aggregation: warp per (node, layer), edge-pair lanes ----------------
__global__ __launch_bounds__(256) void aggregate(int N) {
    const int layer = blockIdx.y;
    const int d = blockIdx.x * 8 + (threadIdx.x >> 5);
    const int lane = threadIdx.x & 31;
    if (d >= N) return;

    const __half* __restrict__ hbase = g_hh + (size_t)layer * NMAX * 128;
    const float* __restrict__ asb = g_as + (size_t)layer * NMAX * 2;
    const float2 adv = __ldg((const float2*)(g_ad + ((size_t)layer * NMAX + d) * 2));
    const float ad0 = adv.x, ad1 = adv.y;

    const int beg = g_off[layer * (NMAX + 1) + d];
    const int cnt = g_off[layer * (NMAX + 1) + d + 1] - beg;
    const int T = cnt + 1;                       // + self loop
    const int* __restrict__ sl = g_srclist + (size_t)layer * ECAP + beg;

    const int sub = lane >> 4;
    const int l16 = lane & 15;
    const int head1 = (l16 >= 8);

    float acc[8] = {0.f, 0.f, 0.f, 0.f, 0.f, 0.f, 0.f, 0.f};
    float den = 0.f;

    int i = 0;
    for (; i + 4 <= T; i += 4) {
        int sA0 = (i     < cnt) ? __ldg(&sl[i])     : d;
        int sA1 = (i + 1 < cnt) ? __ldg(&sl[i + 1]) : d;
        int sB0 = (i + 2 < cnt) ? __ldg(&sl[i + 2]) : d;
        int sB1 = (i + 3 < cnt) ? __ldg(&sl[i + 3]) : d;
        int sA = sub ? sA1 : sA0;
        int sB = sub ? sB1 : sB0;
        float2 aA = __ldg((const float2*)(asb + (size_t)sA * 2));
        float2 aB = __ldg((const float2*)(asb + (size_t)sB * 2));
        uint4 qA = __ldg((const uint4*)(hbase + (size_t)sA * 128 + l16 * 8));
        uint4 qB = __ldg((const uint4*)(hbase + (size_t)sB * 128 + l16 * 8));

        float uA0 = __expf(lrelu(aA.x + ad0)), uA1 = __expf(lrelu(aA.y + ad1));
        float uB0 = __expf(lrelu(aB.x + ad0)), uB1 = __expf(lrelu(aB.y + ad1));
        float uA = head1 ? uA1 : uA0;
        float uB = head1 ? uB1 : uB0;
        den += uA + uB;
        const __half2* hA = (const __half2*)&qA;
        const __half2* hB = (const __half2*)&qB;
        #pragma unroll
        for (int j = 0; j < 4; j++) {
            float2 fA = __half22float2(hA[j]);
            float2 fB = __half22float2(hB[j]);
            acc[2 * j]     += uA * fA.x + uB * fB.x;
            acc[2 * j + 1] += uA * fA.y + uB * fB.y;
        }
    }
    if (i + 2 <= T) {
        int s0 = (i     < cnt) ? __ldg(&sl[i])     : d;
        int s1 = (i + 1 < cnt) ? __ldg(&sl[i + 1]) : d;
        int s = sub ? s1 : s0;
        float2 a = __ldg((const float2*)(asb + (size_t)s * 2));
        uint4 qv = __ldg((const uint4*)(hbase + (size_t)s * 128 + l16 * 8));
        float u0 = __expf(lrelu(a.x + ad0)), u1 = __expf(lrelu(a.y + ad1));
        float u = head1 ? u1 : u0;
        den += u;
        const __half2* hq = (const __half2*)&qv;
        #pragma unroll
        for (int j = 0; j < 4; j++) {
            float2 f = __half22float2(hq[j]);
            acc[2 * j]     += u * f.x;
            acc[2 * j + 1] += u * f.y;
        }
        i += 2;
    }
    if (i < T) {
        int s = (i < cnt) ? __ldg(&sl[i]) : d;
        float2 a = __ldg((const float2*)(asb + (size_t)s * 2));
        uint4 qv = __ldg((const uint4*)(hbase + (size_t)s * 128 + l16 * 8));
        float u0 = __expf(lrelu(a.x + ad0)), u1 = __expf(lrelu(a.y + ad1));
        float u = head1 ? u1 : u0;
        if (sub) u = 0.f;
        den += u;
        const __half2* hq = (const __half2*)&qv;
        #pragma unroll
        for (int j = 0; j < 4; j++) {
            float2 f = __half22float2(hq[j]);
            acc[2 * j]     += u * f.x;
            acc[2 * j + 1] += u * f.y;
        }
    }

    #pragma unroll
    for (int j = 0; j < 8; j++) acc[j] += __shfl_xor_sync(0xffffffffu, acc[j], 16);
    den += __shfl_xor_sync(0xffffffffu, den, 16);

    const float inv = 1.f / den;
    float* outp = g_out + ((size_t)layer * NMAX + d) * 128 + l16 * 8 + sub * 4;
    float4 v;
    if (sub) v = make_float4(acc[4] * inv, acc[5] * inv, acc[6] * inv, acc[7] * inv);
    else     v = make_float4(acc[0] * inv, acc[1] * inv, acc[2] * inv, acc[3] * inv);
    *(float4*)outp = v;
}

// ---------------- final FC (tensor core), pre-converted tf32 smem ----------------
__global__ __launch_bounds__(256) void final_gemm_tc(const float* __restrict__ b1,
                                                     const float* __restrict__ b2,
                                                     const float* __restrict__ fcW,
                                                     const float* __restrict__ fcb,
                                                     float* __restrict__ y,
                                                     int N) {
    __shared__ unsigned As[128][20];
    __shared__ unsigned Bs[16][72];
    const int r0 = blockIdx.x * 128;
    const int tid = threadIdx.x;
    const int wid = tid >> 5, lane = tid & 31;
    const int gid = lane >> 2, q = lane & 3;
    const int m0w = wid * 16;

    float c[8][4];
    #pragma unroll
    for (int j = 0; j < 8; j++)
        #pragma unroll
        for (int k = 0; k < 4; k++) c[j][k] = 0.f;

    for (int k0 = 0; k0 < 256; k0 += 16) {
        const int sel = (k0 >= 128);
        const float* __restrict__ bias = sel ? b2 : b1;
        const int kb = k0 - sel * 128;
        const float* __restrict__ src = g_out + (size_t)sel * NMAX * 128;
        #pragma unroll
        for (int i = 0; i < 2; i++) {
            int lin = tid + i * 256;
            int row = lin >> 2, c4 = (lin & 3) * 4;
            float4 v = make_float4(0.f, 0.f, 0.f, 0.f);
            int n = r0 + row;
            if (n < N) {
                float4 g = *(const float4*)&src[(size_t)n * 128 + kb + c4];
                float4 bb = *(const float4*)&bias[kb + c4];
                v.x = fmaxf(g.x + bb.x, 0.f);
                v.y = fmaxf(g.y + bb.y, 0.f);
                v.z = fmaxf(g.z + bb.z, 0.f);
                v.w = fmaxf(g.w + bb.w, 0.f);
            }
            uint4 u = make_uint4(f2tf32(v.x), f2tf32(v.y), f2tf32(v.z), f2tf32(v.w));
            *(uint4*)&As[row][c4] = u;
        }
        {
            int kk = tid >> 4, n4 = (tid & 15) * 4;
            float4 v = *(const float4*)&fcW[(size_t)(k0 + kk) * 64 + n4];
            uint4 u = make_uint4(f2tf32(v.x), f2tf32(v.y), f2tf32(v.z), f2tf32(v.w));
            *(uint4*)&Bs[kk][n4] = u;
        }
        __syncthreads();

        #pragma unroll
        for (int sub = 0; sub < 2; sub++) {
            const int kk = sub * 8;
            unsigned a[4], b[8][2];
            int m = m0w + gid;
            a[0] = As[m][kk + q];
            a[1] = As[m + 8][kk + q];
            a[2] = As[m][kk + q + 4];
            a[3] = As[m + 8][kk + q + 4];
            #pragma unroll
            for (int nt = 0; nt < 8; nt++) {
                int n = nt * 8 + gid;
                b[nt][0] = Bs[kk + q][n];
                b[nt][1] = Bs[kk + q + 4][n];
            }
            #pragma unroll
            for (int nt = 0; nt < 8; nt++) mma_tf32(c[nt], a, b[nt]);
        }
        __syncthreads();
    }

    #pragma unroll
    for (int nt = 0; nt < 8; nt++) {
        int col = nt * 8 + 2 * q;
        float2 fb = *(const float2*)&fcb[col];
        int r = r0 + m0w + gid;
        if (r < N) {
            float2 v = make_float2(c[nt][0] + fb.x, c[nt][1] + fb.y);
            *(float2*)&y[(size_t)r * 64 + col] = v;
        }
        if (r + 8 < N) {
            float2 v = make_float2(c[nt][2] + fb.x, c[nt][3] + fb.y);
            *(float2*)&y[(size_t)(r + 8) * 64 + col] = v;
        }
    }
}

// ---------------- launcher: fork CSR build onto a side stream ----------------
extern "C" void kernel_launch(void* const* d_in, const int* in_sizes, int n_in,
                              void* d_out, int out_size) {
    const float* x    = (const float*)d_in[0];
    const int*   eic  = (const int*)  d_in[1];
    const int*   eil  = (const int*)  d_in[2];
    const float* W1   = (const float*)d_in[3];
    const float* as1  = (const float*)d_in[4];
    const float* ad1  = (const float*)d_in[5];
    const float* b1   = (const float*)d_in[6];
    const float* W2   = (const float*)d_in[7];
    const float* as2  = (const float*)d_in[8];
    const float* ad2  = (const float*)d_in[9];
    const float* b2   = (const float*)d_in[10];
    const float* fcW  = (const float*)d_in[11];
    const float* fcb  = (const float*)d_in[12];
    float* y = (float*)d_out;

    const int N  = in_sizes[0] / 256;
    const int E1 = in_sizes[1] / 2;
    const int E2 = in_sizes[2] / 2;
    const int nblk = (N + SCAN_CHUNK - 1) / SCAN_CHUNK;   // <= MAXBLK

    static cudaStream_t s2 = nullptr;
    static cudaEvent_t evFork = nullptr, evJoin = nullptr;
    if (s2 == nullptr) {
        cudaStreamCreateWithFlags(&s2, cudaStreamNonBlocking);
        cudaEventCreateWithFlags(&evFork, cudaEventDisableTiming);
        cudaEventCreateWithFlags(&evJoin, cudaEventDisableTiming);
    }

    // fork: CSR build chain on s2, independent of the GEMM path
    cudaEventRecord(evFork, 0);
    cudaStreamWaitEvent(s2, evFork, 0);

    zero_deg<<<(2 * NMAX + 255) / 256, 256, 0, s2>>>();
    count_kernel<<<(E1 / 4 + 255) / 256 + 1, 256, 0, s2>>>(eic, E1, 0);
    count_kernel<<<(E2 / 4 + 255) / 256 + 1, 256, 0, s2>>>(eil, E2, 1);
    scan_partial<<<dim3(nblk, 2), 256, 0, s2>>>(N);
    scan_tops<<<2, 128, 0, s2>>>(nblk, N);
    scan_final<<<dim3(nblk, 2), 256, 0, s2>>>(N);
    scatter_kernel<<<(E1 / 4 + 255) / 256 + 1, 256, 0, s2>>>(eic, E1, 0);
    scatter_kernel<<<(E2 / 4 + 255) / 256 + 1, 256, 0, s2>>>(eil, E2, 1);
    cudaEventRecord(evJoin, s2);

    // main stream: GEMM -> attention logits (overlaps with CSR build)
    gemm_h_tc<<<dim3((N + 127) / 128, 2), 256>>>(x, W1, W2, N);
    att_kernel<<<(N + 7) / 8, 256>>>(as1, ad1, as2, ad2, N);

    // join, then aggregate + final FC
    cudaStreamWaitEvent(0, evJoin, 0);
    aggregate<<<dim3((N + 7) / 8, 2), 256>>>(N);
    final_gemm_tc<<<(N + 127) / 128, 256>>>(b1, b2, fcW, fcb, y, N);
}